// round 1
// baseline (speedup 1.0000x reference)
#include <cuda_runtime.h>

// ---------------------------------------------------------------------------
// MultiHeadAttention: B=2, S=2048, D=1024, H=16, DK=DV=64
//   Qp = q@Wq^T+bq ; Kp = k@Wk^T+bk ; Vp = v@Wv^T+bv   (per-head [B,H,S,64])
//   scores = Qp Kp^T * 0.125 + prev ; mask -> -inf ; softmax ; @Vp
//   out = attn @ Wo^T + bo
// ---------------------------------------------------------------------------

namespace {
constexpr int  Bb    = 2;
constexpr int  S     = 2048;
constexpr int  D     = 1024;
constexpr int  H     = 16;
constexpr int  M     = Bb * S;        // 4096 rows
constexpr float SCALE = 0.125f;       // 64^-0.5
}

// Scratch (allocation-free: __device__ globals)
__device__ float g_Qp[Bb * H * S * 64];     // 16 MB, [B,H,S,64]
__device__ float g_Kp[Bb * H * S * 64];
__device__ float g_Vp[Bb * H * S * 64];
__device__ float g_attn[(size_t)M * D];     // 16 MB, [B,S, H*64]
__device__ unsigned char g_maskb[M];        // normalized key_padding_mask

// ---------------------------------------------------------------------------
// Mask normalization: sniff storage dtype (bool/u8 vs int32 vs float32) from
// byte patterns, then expand to uint8 flags. All reads in-bounds for every
// candidate dtype (we only touch the first 4096 bytes in the sniff phase).
// ---------------------------------------------------------------------------
__global__ void mask_prepare_kernel(const unsigned char* __restrict__ raw)
{
    __shared__ int flags;
    if (threadIdx.x == 0) flags = 0;
    __syncthreads();

    int f = 0;
    for (int i = threadIdx.x; i < M; i += blockDim.x) {
        unsigned char c = raw[i];
        if ((i & 3) != 0 && c != 0) f |= 1;        // misaligned nonzero -> bytes
        if ((i & 3) == 3 && c == 0x3F) f |= 2;     // fp32 1.0f signature -> floats
    }
    if (f) atomicOr(&flags, f);
    __syncthreads();

    const int fl = flags;
    for (int i = threadIdx.x; i < M; i += blockDim.x) {
        unsigned char v;
        if (fl & 2)      v = (((const float*)raw)[i] != 0.0f);
        else if (fl & 1) v = (raw[i] != 0);
        else             v = (((const int*)raw)[i] != 0);
        g_maskb[i] = v;
    }
}

// ---------------------------------------------------------------------------
// fp32 GEMM: out[m,n] = sum_k X[m,k] * W[n,k] + bias[n]
// M=4096, N=1024, K=1024. 128x128 block tile, BK=16, 256 thr, 8x8 per thread.
// bhsd=true writes into per-head [B,H,S,64] layout.
// ---------------------------------------------------------------------------
__device__ __forceinline__ void gemm128(
    const float* __restrict__ X, const float* __restrict__ W,
    const float* __restrict__ bias, float* __restrict__ dst, bool bhsd)
{
    __shared__ float As[16][128];
    __shared__ float Bs[16][128];

    const int tid = threadIdx.x;
    const int tx  = tid & 15;
    const int ty  = tid >> 4;
    const int m0  = blockIdx.y * 128;
    const int n0  = blockIdx.x * 128;

    float acc[8][8];
#pragma unroll
    for (int i = 0; i < 8; ++i)
#pragma unroll
        for (int j = 0; j < 8; ++j) acc[i][j] = 0.f;

    for (int k0 = 0; k0 < 1024; k0 += 16) {
#pragma unroll
        for (int it = 0; it < 2; ++it) {
            int idx = tid + it * 256;
            int row = idx >> 2;
            int kq  = (idx & 3) * 4;
            float4 a = *(const float4*)(X + (size_t)(m0 + row) * 1024 + k0 + kq);
            As[kq + 0][row] = a.x; As[kq + 1][row] = a.y;
            As[kq + 2][row] = a.z; As[kq + 3][row] = a.w;
            float4 b = *(const float4*)(W + (size_t)(n0 + row) * 1024 + k0 + kq);
            Bs[kq + 0][row] = b.x; Bs[kq + 1][row] = b.y;
            Bs[kq + 2][row] = b.z; Bs[kq + 3][row] = b.w;
        }
        __syncthreads();
#pragma unroll
        for (int kk = 0; kk < 16; ++kk) {
            float a[8], bb[8];
            *(float4*)(a)      = *(const float4*)&As[kk][ty * 8];
            *(float4*)(a + 4)  = *(const float4*)&As[kk][ty * 8 + 4];
            *(float4*)(bb)     = *(const float4*)&Bs[kk][tx * 8];
            *(float4*)(bb + 4) = *(const float4*)&Bs[kk][tx * 8 + 4];
#pragma unroll
            for (int i = 0; i < 8; ++i)
#pragma unroll
                for (int j = 0; j < 8; ++j)
                    acc[i][j] = fmaf(a[i], bb[j], acc[i][j]);
        }
        __syncthreads();
    }

#pragma unroll
    for (int i = 0; i < 8; ++i) {
        int m    = m0 + ty * 8 + i;
        int bidx = m >> 11;          // / S
        int s    = m & 2047;         // % S
#pragma unroll
        for (int j = 0; j < 8; j += 4) {
            int n = n0 + tx * 8 + j;
            float4 val;
            val.x = acc[i][j]     + bias[n];
            val.y = acc[i][j + 1] + bias[n + 1];
            val.z = acc[i][j + 2] + bias[n + 2];
            val.w = acc[i][j + 3] + bias[n + 3];
            if (bhsd) {
                int h = n >> 6, d = n & 63;   // float4 never crosses a head
                *(float4*)(dst + (((size_t)(bidx * H + h) * S + s) << 6) + d) = val;
            } else {
                *(float4*)(dst + (size_t)m * 1024 + n) = val;
            }
        }
    }
}

__global__ void __launch_bounds__(256) qkv_proj_kernel(
    const float* __restrict__ q, const float* __restrict__ k, const float* __restrict__ v,
    const float* __restrict__ Wq, const float* __restrict__ bq,
    const float* __restrict__ Wk, const float* __restrict__ bk,
    const float* __restrict__ Wv, const float* __restrict__ bv)
{
    const float *X, *W, *bias;
    float* dst;
    if (blockIdx.z == 0)      { X = q; W = Wq; bias = bq; dst = g_Qp; }
    else if (blockIdx.z == 1) { X = k; W = Wk; bias = bk; dst = g_Kp; }
    else                      { X = v; W = Wv; bias = bv; dst = g_Vp; }
    gemm128(X, W, bias, dst, true);
}

__global__ void __launch_bounds__(256) out_proj_kernel(
    const float* __restrict__ Wo, const float* __restrict__ bo, float* __restrict__ out)
{
    gemm128(g_attn, Wo, bo, out, false);
}

// ---------------------------------------------------------------------------
// Flash attention: one block = (head bh, 64 q-rows). Iterate 64-col kv tiles.
// scores = Qp Kp^T * SCALE + prev; masked -> -1e30; online softmax; @ Vp.
// 256 threads, 4x4 score/out tiles per thread. 48 KB static smem.
// ---------------------------------------------------------------------------
__global__ void __launch_bounds__(256) flash_kernel(const float* __restrict__ prev)
{
    __shared__ float Qs[64][64];   // [k][r]  (transposed)
    __shared__ float KP[64][64];   // K as [k][t]; reused as P [c][r]
    __shared__ float Vs[64][64];   // [c][dv]

    const int tid = threadIdx.x;
    const int tx  = tid & 15;
    const int ty  = tid >> 4;
    const int bh  = blockIdx.y;          // b*H + h
    const int b   = bh >> 4;
    const int hq  = bh & 15;
    const int q0  = blockIdx.x * 64;

    const float* Qbase    = g_Qp + ((size_t)bh * S + q0) * 64;
    const float* Kbase    = g_Kp + (size_t)bh * S * 64;
    const float* Vbase    = g_Vp + (size_t)bh * S * 64;
    const float* prevBase = prev + ((size_t)bh * S + q0) * S;

    // Load Q tile (transposed) once
#pragma unroll
    for (int it = 0; it < 4; ++it) {
        int idx = tid + it * 256;
        int r   = idx >> 4;
        int kq  = (idx & 15) * 4;
        float4 a = *(const float4*)(Qbase + r * 64 + kq);
        Qs[kq + 0][r] = a.x; Qs[kq + 1][r] = a.y;
        Qs[kq + 2][r] = a.z; Qs[kq + 3][r] = a.w;
    }

    float m_i[4], l_i[4], oacc[4][4];
#pragma unroll
    for (int i = 0; i < 4; ++i) {
        m_i[i] = -3.0e38f;
        l_i[i] = 0.f;
#pragma unroll
        for (int j = 0; j < 4; ++j) oacc[i][j] = 0.f;
    }

    for (int t0 = 0; t0 < S; t0 += 64) {
        __syncthreads();   // protect KP reuse from previous AV phase
#pragma unroll
        for (int it = 0; it < 4; ++it) {
            int idx = tid + it * 256;
            int r   = idx >> 4;
            int kq  = (idx & 15) * 4;
            float4 a = *(const float4*)(Kbase + (size_t)(t0 + r) * 64 + kq);
            KP[kq + 0][r] = a.x; KP[kq + 1][r] = a.y;
            KP[kq + 2][r] = a.z; KP[kq + 3][r] = a.w;
            float4 vv = *(const float4*)(Vbase + (size_t)(t0 + r) * 64 + kq);
            *(float4*)&Vs[r][kq] = vv;
        }
        __syncthreads();

        // scores (raw QK^T)
        float p[4][4];
#pragma unroll
        for (int i = 0; i < 4; ++i)
#pragma unroll
            for (int j = 0; j < 4; ++j) p[i][j] = 0.f;
#pragma unroll
        for (int kk = 0; kk < 64; ++kk) {
            float a[4], bb[4];
            *(float4*)a  = *(const float4*)&Qs[kk][ty * 4];
            *(float4*)bb = *(const float4*)&KP[kk][tx * 4];
#pragma unroll
            for (int i = 0; i < 4; ++i)
#pragma unroll
                for (int j = 0; j < 4; ++j)
                    p[i][j] = fmaf(a[i], bb[j], p[i][j]);
        }

        // scale + prev residual + key-padding mask
        const uchar4 mk = *(const uchar4*)(g_maskb + b * S + t0 + tx * 4);
#pragma unroll
        for (int i = 0; i < 4; ++i) {
            float4 pv = *(const float4*)(prevBase + (size_t)(ty * 4 + i) * S + t0 + tx * 4);
            p[i][0] = mk.x ? -1.0e30f : fmaf(p[i][0], SCALE, pv.x);
            p[i][1] = mk.y ? -1.0e30f : fmaf(p[i][1], SCALE, pv.y);
            p[i][2] = mk.z ? -1.0e30f : fmaf(p[i][2], SCALE, pv.z);
            p[i][3] = mk.w ? -1.0e30f : fmaf(p[i][3], SCALE, pv.w);
        }

        // online softmax (row stats reduced across the 16 tx lanes; xor<=8
        // stays inside each 16-lane half-warp)
#pragma unroll
        for (int i = 0; i < 4; ++i) {
            float mx = fmaxf(fmaxf(p[i][0], p[i][1]), fmaxf(p[i][2], p[i][3]));
#pragma unroll
            for (int o = 8; o; o >>= 1) mx = fmaxf(mx, __shfl_xor_sync(0xffffffffu, mx, o));
            float m_new = fmaxf(m_i[i], mx);
            float corr  = __expf(m_i[i] - m_new);
            float rs = 0.f;
#pragma unroll
            for (int j = 0; j < 4; ++j) { p[i][j] = __expf(p[i][j] - m_new); rs += p[i][j]; }
#pragma unroll
            for (int o = 8; o; o >>= 1) rs += __shfl_xor_sync(0xffffffffu, rs, o);
            l_i[i] = l_i[i] * corr + rs;
            m_i[i] = m_new;
#pragma unroll
            for (int j = 0; j < 4; ++j) oacc[i][j] *= corr;
        }

        // P through smem (reuse KP) as [c][r], then AV
        __syncthreads();
#pragma unroll
        for (int i = 0; i < 4; ++i)
#pragma unroll
            for (int j = 0; j < 4; ++j)
                KP[tx * 4 + j][ty * 4 + i] = p[i][j];
        __syncthreads();

#pragma unroll
        for (int cc = 0; cc < 64; ++cc) {
            float a[4], bb[4];
            *(float4*)a  = *(const float4*)&KP[cc][ty * 4];
            *(float4*)bb = *(const float4*)&Vs[cc][tx * 4];
#pragma unroll
            for (int i = 0; i < 4; ++i)
#pragma unroll
                for (int j = 0; j < 4; ++j)
                    oacc[i][j] = fmaf(a[i], bb[j], oacc[i][j]);
        }
    }

    // epilogue -> g_attn [B,S,H*64]
#pragma unroll
    for (int i = 0; i < 4; ++i) {
        float inv = 1.0f / fmaxf(l_i[i], 1e-30f);
        int s = q0 + ty * 4 + i;
        float4 o4;
        o4.x = oacc[i][0] * inv;
        o4.y = oacc[i][1] * inv;
        o4.z = oacc[i][2] * inv;
        o4.w = oacc[i][3] * inv;
        *(float4*)(g_attn + ((size_t)b * S + s) * 1024 + hq * 64 + tx * 4) = o4;
    }
}

// ---------------------------------------------------------------------------
// Launch: mask-normalize -> QKV projections -> flash attention -> out proj
// Inputs: 0:q 1:k 2:v 3:prev 4:key_padding_mask 5:Wq 6:bq 7:Wk 8:bk 9:Wv 10:bv
//         11:Wo 12:bo
// ---------------------------------------------------------------------------
extern "C" void kernel_launch(void* const* d_in, const int* in_sizes, int n_in,
                              void* d_out, int out_size)
{
    (void)in_sizes; (void)n_in; (void)out_size;

    const float* q    = (const float*)d_in[0];
    const float* k    = (const float*)d_in[1];
    const float* v    = (const float*)d_in[2];
    const float* prev = (const float*)d_in[3];
    const unsigned char* mask = (const unsigned char*)d_in[4];
    const float* Wq = (const float*)d_in[5];
    const float* bq = (const float*)d_in[6];
    const float* Wk = (const float*)d_in[7];
    const float* bk = (const float*)d_in[8];
    const float* Wv = (const float*)d_in[9];
    const float* bv = (const float*)d_in[10];
    const float* Wo = (const float*)d_in[11];
    const float* bo = (const float*)d_in[12];
    float* out = (float*)d_out;

    mask_prepare_kernel<<<1, 256>>>(mask);
    qkv_proj_kernel<<<dim3(1024 / 128, M / 128, 3), 256>>>(q, k, v, Wq, bq, Wk, bk, Wv, bv);
    flash_kernel<<<dim3(S / 64, Bb * H), 256>>>(prev);
    out_proj_kernel<<<dim3(1024 / 128, M / 128), 256>>>(Wo, bo, out);
}

// round 2
// speedup vs baseline: 1.0010x; 1.0010x over previous
#include <cuda_runtime.h>

// ---------------------------------------------------------------------------
// MultiHeadAttention: B=2, S=2048, D=1024, H=16, DK=DV=64
//   Qp = q@Wq^T+bq ; Kp = k@Wk^T+bk ; Vp = v@Wv^T+bv   (per-head [B,H,S,64])
//   scores = Qp Kp^T * 0.125 + prev ; mask -> -inf ; softmax ; @Vp
//   out = attn @ Wo^T + bo
// ---------------------------------------------------------------------------

namespace {
constexpr int  Bb    = 2;
constexpr int  S     = 2048;
constexpr int  D     = 1024;
constexpr int  H     = 16;
constexpr int  M     = Bb * S;        // 4096 rows
constexpr float SCALE = 0.125f;       // 64^-0.5
}

// Scratch (allocation-free: __device__ globals)
__device__ float g_Qp[Bb * H * S * 64];     // 16 MB, [B,H,S,64]
__device__ float g_Kp[Bb * H * S * 64];
__device__ float g_Vp[Bb * H * S * 64];
__device__ float g_attn[(size_t)M * D];     // 16 MB, [B,S, H*64]
__device__ unsigned char g_maskb[M];        // normalized key_padding_mask

// ---------------------------------------------------------------------------
// Mask normalization: sniff storage dtype (bool/u8 vs int32 vs float32) from
// byte patterns, then expand to uint8 flags. All reads in-bounds for every
// candidate dtype (we only touch the first 4096 bytes in the sniff phase).
// ---------------------------------------------------------------------------
__global__ void mask_prepare_kernel(const unsigned char* __restrict__ raw)
{
    __shared__ int flags;
    if (threadIdx.x == 0) flags = 0;
    __syncthreads();

    int f = 0;
    for (int i = threadIdx.x; i < M; i += blockDim.x) {
        unsigned char c = raw[i];
        if ((i & 3) != 0 && c != 0) f |= 1;        // misaligned nonzero -> bytes
        if ((i & 3) == 3 && c == 0x3F) f |= 2;     // fp32 1.0f signature -> floats
    }
    if (f) atomicOr(&flags, f);
    __syncthreads();

    const int fl = flags;
    for (int i = threadIdx.x; i < M; i += blockDim.x) {
        unsigned char v;
        if (fl & 2)      v = (((const float*)raw)[i] != 0.0f);
        else if (fl & 1) v = (raw[i] != 0);
        else             v = (((const int*)raw)[i] != 0);
        g_maskb[i] = v;
    }
}

// ---------------------------------------------------------------------------
// fp32 GEMM: out[m,n] = sum_k X[m,k] * W[n,k] + bias[n]
// M=4096, N=1024, K=1024. 128x128 block tile, BK=16, 256 thr, 8x8 per thread.
// bhsd=true writes into per-head [B,H,S,64] layout.
// ---------------------------------------------------------------------------
__device__ __forceinline__ void gemm128(
    const float* __restrict__ X, const float* __restrict__ W,
    const float* __restrict__ bias, float* __restrict__ dst, bool bhsd)
{
    __shared__ float As[16][128];
    __shared__ float Bs[16][128];

    const int tid = threadIdx.x;
    const int tx  = tid & 15;
    const int ty  = tid >> 4;
    const int m0  = blockIdx.y * 128;
    const int n0  = blockIdx.x * 128;

    float acc[8][8];
#pragma unroll
    for (int i = 0; i < 8; ++i)
#pragma unroll
        for (int j = 0; j < 8; ++j) acc[i][j] = 0.f;

    for (int k0 = 0; k0 < 1024; k0 += 16) {
#pragma unroll
        for (int it = 0; it < 2; ++it) {
            int idx = tid + it * 256;
            int row = idx >> 2;
            int kq  = (idx & 3) * 4;
            float4 a = *(const float4*)(X + (size_t)(m0 + row) * 1024 + k0 + kq);
            As[kq + 0][row] = a.x; As[kq + 1][row] = a.y;
            As[kq + 2][row] = a.z; As[kq + 3][row] = a.w;
            float4 b = *(const float4*)(W + (size_t)(n0 + row) * 1024 + k0 + kq);
            Bs[kq + 0][row] = b.x; Bs[kq + 1][row] = b.y;
            Bs[kq + 2][row] = b.z; Bs[kq + 3][row] = b.w;
        }
        __syncthreads();
#pragma unroll
        for (int kk = 0; kk < 16; ++kk) {
            float a[8], bb[8];
            *(float4*)(a)      = *(const float4*)&As[kk][ty * 8];
            *(float4*)(a + 4)  = *(const float4*)&As[kk][ty * 8 + 4];
            *(float4*)(bb)     = *(const float4*)&Bs[kk][tx * 8];
            *(float4*)(bb + 4) = *(const float4*)&Bs[kk][tx * 8 + 4];
#pragma unroll
            for (int i = 0; i < 8; ++i)
#pragma unroll
                for (int j = 0; j < 8; ++j)
                    acc[i][j] = fmaf(a[i], bb[j], acc[i][j]);
        }
        __syncthreads();
    }

#pragma unroll
    for (int i = 0; i < 8; ++i) {
        int m    = m0 + ty * 8 + i;
        int bidx = m >> 11;          // / S
        int s    = m & 2047;         // % S
#pragma unroll
        for (int j = 0; j < 8; j += 4) {
            int n = n0 + tx * 8 + j;
            float4 val;
            val.x = acc[i][j]     + bias[n];
            val.y = acc[i][j + 1] + bias[n + 1];
            val.z = acc[i][j + 2] + bias[n + 2];
            val.w = acc[i][j + 3] + bias[n + 3];
            if (bhsd) {
                int h = n >> 6, d = n & 63;   // float4 never crosses a head
                *(float4*)(dst + (((size_t)(bidx * H + h) * S + s) << 6) + d) = val;
            } else {
                *(float4*)(dst + (size_t)m * 1024 + n) = val;
            }
        }
    }
}

__global__ void __launch_bounds__(256) qkv_proj_kernel(
    const float* __restrict__ q, const float* __restrict__ k, const float* __restrict__ v,
    const float* __restrict__ Wq, const float* __restrict__ bq,
    const float* __restrict__ Wk, const float* __restrict__ bk,
    const float* __restrict__ Wv, const float* __restrict__ bv)
{
    const float *X, *W, *bias;
    float* dst;
    if (blockIdx.z == 0)      { X = q; W = Wq; bias = bq; dst = g_Qp; }
    else if (blockIdx.z == 1) { X = k; W = Wk; bias = bk; dst = g_Kp; }
    else                      { X = v; W = Wv; bias = bv; dst = g_Vp; }
    gemm128(X, W, bias, dst, true);
}

__global__ void __launch_bounds__(256) out_proj_kernel(
    const float* __restrict__ Wo, const float* __restrict__ bo, float* __restrict__ out)
{
    gemm128(g_attn, Wo, bo, out, false);
}

// ---------------------------------------------------------------------------
// Flash attention: one block = (head bh, 64 q-rows). Iterate 64-col kv tiles.
// scores = Qp Kp^T * SCALE + prev; masked -> -1e30; online softmax; @ Vp.
// 256 threads, 4x4 score/out tiles per thread. 48 KB static smem.
// ---------------------------------------------------------------------------
__global__ void __launch_bounds__(256) flash_kernel(const float* __restrict__ prev)
{
    __shared__ float Qs[64][64];   // [k][r]  (transposed)
    __shared__ float KP[64][64];   // K as [k][t]; reused as P [c][r]
    __shared__ float Vs[64][64];   // [c][dv]

    const int tid = threadIdx.x;
    const int tx  = tid & 15;
    const int ty  = tid >> 4;
    const int bh  = blockIdx.y;          // b*H + h
    const int b   = bh >> 4;
    const int hq  = bh & 15;
    const int q0  = blockIdx.x * 64;

    const float* Qbase    = g_Qp + ((size_t)bh * S + q0) * 64;
    const float* Kbase    = g_Kp + (size_t)bh * S * 64;
    const float* Vbase    = g_Vp + (size_t)bh * S * 64;
    const float* prevBase = prev + ((size_t)bh * S + q0) * S;

    // Load Q tile (transposed) once
#pragma unroll
    for (int it = 0; it < 4; ++it) {
        int idx = tid + it * 256;
        int r   = idx >> 4;
        int kq  = (idx & 15) * 4;
        float4 a = *(const float4*)(Qbase + r * 64 + kq);
        Qs[kq + 0][r] = a.x; Qs[kq + 1][r] = a.y;
        Qs[kq + 2][r] = a.z; Qs[kq + 3][r] = a.w;
    }

    float m_i[4], l_i[4], oacc[4][4];
#pragma unroll
    for (int i = 0; i < 4; ++i) {
        m_i[i] = -3.0e38f;
        l_i[i] = 0.f;
#pragma unroll
        for (int j = 0; j < 4; ++j) oacc[i][j] = 0.f;
    }

    for (int t0 = 0; t0 < S; t0 += 64) {
        __syncthreads();   // protect KP reuse from previous AV phase
#pragma unroll
        for (int it = 0; it < 4; ++it) {
            int idx = tid + it * 256;
            int r   = idx >> 4;
            int kq  = (idx & 15) * 4;
            float4 a = *(const float4*)(Kbase + (size_t)(t0 + r) * 64 + kq);
            KP[kq + 0][r] = a.x; KP[kq + 1][r] = a.y;
            KP[kq + 2][r] = a.z; KP[kq + 3][r] = a.w;
            float4 vv = *(const float4*)(Vbase + (size_t)(t0 + r) * 64 + kq);
            *(float4*)&Vs[r][kq] = vv;
        }
        __syncthreads();

        // scores (raw QK^T)
        float p[4][4];
#pragma unroll
        for (int i = 0; i < 4; ++i)
#pragma unroll
            for (int j = 0; j < 4; ++j) p[i][j] = 0.f;
#pragma unroll
        for (int kk = 0; kk < 64; ++kk) {
            float a[4], bb[4];
            *(float4*)a  = *(const float4*)&Qs[kk][ty * 4];
            *(float4*)bb = *(const float4*)&KP[kk][tx * 4];
#pragma unroll
            for (int i = 0; i < 4; ++i)
#pragma unroll
                for (int j = 0; j < 4; ++j)
                    p[i][j] = fmaf(a[i], bb[j], p[i][j]);
        }

        // scale + prev residual + key-padding mask
        const uchar4 mk = *(const uchar4*)(g_maskb + b * S + t0 + tx * 4);
#pragma unroll
        for (int i = 0; i < 4; ++i) {
            float4 pv = *(const float4*)(prevBase + (size_t)(ty * 4 + i) * S + t0 + tx * 4);
            p[i][0] = mk.x ? -1.0e30f : fmaf(p[i][0], SCALE, pv.x);
            p[i][1] = mk.y ? -1.0e30f : fmaf(p[i][1], SCALE, pv.y);
            p[i][2] = mk.z ? -1.0e30f : fmaf(p[i][2], SCALE, pv.z);
            p[i][3] = mk.w ? -1.0e30f : fmaf(p[i][3], SCALE, pv.w);
        }

        // online softmax (row stats reduced across the 16 tx lanes; xor<=8
        // stays inside each 16-lane half-warp)
#pragma unroll
        for (int i = 0; i < 4; ++i) {
            float mx = fmaxf(fmaxf(p[i][0], p[i][1]), fmaxf(p[i][2], p[i][3]));
#pragma unroll
            for (int o = 8; o; o >>= 1) mx = fmaxf(mx, __shfl_xor_sync(0xffffffffu, mx, o));
            float m_new = fmaxf(m_i[i], mx);
            float corr  = __expf(m_i[i] - m_new);
            float rs = 0.f;
#pragma unroll
            for (int j = 0; j < 4; ++j) { p[i][j] = __expf(p[i][j] - m_new); rs += p[i][j]; }
#pragma unroll
            for (int o = 8; o; o >>= 1) rs += __shfl_xor_sync(0xffffffffu, rs, o);
            l_i[i] = l_i[i] * corr + rs;
            m_i[i] = m_new;
#pragma unroll
            for (int j = 0; j < 4; ++j) oacc[i][j] *= corr;
        }

        // P through smem (reuse KP) as [c][r], then AV
        __syncthreads();
#pragma unroll
        for (int i = 0; i < 4; ++i)
#pragma unroll
            for (int j = 0; j < 4; ++j)
                KP[tx * 4 + j][ty * 4 + i] = p[i][j];
        __syncthreads();

#pragma unroll
        for (int cc = 0; cc < 64; ++cc) {
            float a[4], bb[4];
            *(float4*)a  = *(const float4*)&KP[cc][ty * 4];
            *(float4*)bb = *(const float4*)&Vs[cc][tx * 4];
#pragma unroll
            for (int i = 0; i < 4; ++i)
#pragma unroll
                for (int j = 0; j < 4; ++j)
                    oacc[i][j] = fmaf(a[i], bb[j], oacc[i][j]);
        }
    }

    // epilogue -> g_attn [B,S,H*64]
#pragma unroll
    for (int i = 0; i < 4; ++i) {
        float inv = 1.0f / fmaxf(l_i[i], 1e-30f);
        int s = q0 + ty * 4 + i;
        float4 o4;
        o4.x = oacc[i][0] * inv;
        o4.y = oacc[i][1] * inv;
        o4.z = oacc[i][2] * inv;
        o4.w = oacc[i][3] * inv;
        *(float4*)(g_attn + ((size_t)b * S + s) * 1024 + hq * 64 + tx * 4) = o4;
    }
}

// ---------------------------------------------------------------------------
// Launch: mask-normalize -> QKV projections -> flash attention -> out proj
// Inputs: 0:q 1:k 2:v 3:prev 4:key_padding_mask 5:Wq 6:bq 7:Wk 8:bk 9:Wv 10:bv
//         11:Wo 12:bo
// ---------------------------------------------------------------------------
extern "C" void kernel_launch(void* const* d_in, const int* in_sizes, int n_in,
                              void* d_out, int out_size)
{
    (void)in_sizes; (void)n_in; (void)out_size;

    const float* q    = (const float*)d_in[0];
    const float* k    = (const float*)d_in[1];
    const float* v    = (const float*)d_in[2];
    const float* prev = (const float*)d_in[3];
    const unsigned char* mask = (const unsigned char*)d_in[4];
    const float* Wq = (const float*)d_in[5];
    const float* bq = (const float*)d_in[6];
    const float* Wk = (const float*)d_in[7];
    const float* bk = (const float*)d_in[8];
    const float* Wv = (const float*)d_in[9];
    const float* bv = (const float*)d_in[10];
    const float* Wo = (const float*)d_in[11];
    const float* bo = (const float*)d_in[12];
    float* out = (float*)d_out;

    mask_prepare_kernel<<<1, 256>>>(mask);
    qkv_proj_kernel<<<dim3(1024 / 128, M / 128, 3), 256>>>(q, k, v, Wq, bq, Wk, bk, Wv, bv);
    flash_kernel<<<dim3(S / 64, Bb * H), 256>>>(prev);
    out_proj_kernel<<<dim3(1024 / 128, M / 128), 256>>>(Wo, bo, out);
}

// round 4
// speedup vs baseline: 1.2985x; 1.2973x over previous
#include <cuda_runtime.h>
#include <cuda_bf16.h>
#include <cstdint>

// ---------------------------------------------------------------------------
// MultiHeadAttention B=2,S=2048,D=1024,H=16,DK=DV=64
// mma.sync(bf16 split) projections + fp32 flash attention.
// ---------------------------------------------------------------------------

namespace {
constexpr int  Bb = 2, S = 2048, D = 1024, H = 16;
constexpr int  M  = Bb * S;                    // 4096
constexpr float SCALE = 0.125f;

constexpr int BM = 128, BN = 128, KCH = 32;    // CTA tile, K chunk (bf16 elems)
constexpr int NC = D / KCH;                    // 32 chunks
constexpr int ROWPAD = 40;                     // bf16 elems per smem row (80 B)
constexpr int TILE_B = 128 * ROWPAD * 2;       // 10240 B per operand tile
constexpr int BUF_B  = 4 * TILE_B;             // Xh,Xl,Wh,Wl
constexpr int SMEM_DYN = 2 * BUF_B;            // 81920 B
}

// ---- device scratch (allocation-free) ----
__device__ __nv_bfloat16 g_xh[3][(size_t)M * D];   // q,k,v split hi
__device__ __nv_bfloat16 g_xl[3][(size_t)M * D];   // lo
__device__ __nv_bfloat16 g_wh[4][(size_t)D * D];   // Wq,Wk,Wv,Wo hi
__device__ __nv_bfloat16 g_wl[4][(size_t)D * D];   // lo
__device__ __nv_bfloat16 g_ah[(size_t)M * D];      // attn out hi
__device__ __nv_bfloat16 g_al[(size_t)M * D];      // attn out lo
__device__ float g_Qp[(size_t)Bb * H * S * 64];    // [bh][s][64]
__device__ float g_Kp[(size_t)Bb * H * S * 64];
__device__ float g_Vp[(size_t)Bb * H * S * 64];
__device__ unsigned char g_maskb[M];

// ---------------------------------------------------------------------------
// helpers
// ---------------------------------------------------------------------------
__device__ __forceinline__ uint32_t smem_u32(const void* p) {
    uint32_t a;
    asm("{ .reg .u64 t; cvta.to.shared.u64 t, %1; cvt.u32.u64 %0, t; }"
        : "=r"(a) : "l"(p));
    return a;
}
__device__ __forceinline__ uint32_t lds32(uint32_t a) {
    uint32_t v;
    asm volatile("ld.shared.b32 %0, [%1];" : "=r"(v) : "r"(a));
    return v;
}
#define MMA16816(Dv, A0, A1, A2, A3, B0, B1)                                   \
    asm volatile(                                                              \
        "mma.sync.aligned.m16n8k16.row.col.f32.bf16.bf16.f32 "                 \
        "{%0,%1,%2,%3}, {%4,%5,%6,%7}, {%8,%9}, {%0,%1,%2,%3};"                \
        : "+f"((Dv)[0]), "+f"((Dv)[1]), "+f"((Dv)[2]), "+f"((Dv)[3])           \
        : "r"(A0), "r"(A1), "r"(A2), "r"(A3), "r"(B0), "r"(B1))

// ---------------------------------------------------------------------------
// Mask normalization (sniff bool/int32/float32 storage)
// ---------------------------------------------------------------------------
__global__ void mask_prepare_kernel(const unsigned char* __restrict__ raw)
{
    __shared__ int flags;
    if (threadIdx.x == 0) flags = 0;
    __syncthreads();
    int f = 0;
    for (int i = threadIdx.x; i < M; i += blockDim.x) {
        unsigned char c = raw[i];
        if ((i & 3) != 0 && c != 0) f |= 1;
        if ((i & 3) == 3 && c == 0x3F) f |= 2;
    }
    if (f) atomicOr(&flags, f);
    __syncthreads();
    const int fl = flags;
    for (int i = threadIdx.x; i < M; i += blockDim.x) {
        unsigned char v;
        if (fl & 2)      v = (((const float*)raw)[i] != 0.0f);
        else if (fl & 1) v = (raw[i] != 0);
        else             v = (((const int*)raw)[i] != 0);
        g_maskb[i] = v;
    }
}

// ---------------------------------------------------------------------------
// fp32 -> bf16 hi/lo split. which: 0..2 -> g_xh/g_xl, 3..6 -> g_wh/g_wl
// ---------------------------------------------------------------------------
__global__ void __launch_bounds__(256) split_kernel(
    const float* __restrict__ src, int which, int n)
{
    __nv_bfloat16 *hi, *lo;
    if (which < 3) { hi = g_xh[which];     lo = g_xl[which];     }
    else           { hi = g_wh[which - 3]; lo = g_wl[which - 3]; }

    int i = (blockIdx.x * blockDim.x + threadIdx.x) * 4;
    if (i < n) {
        float4 v = *(const float4*)(src + i);
        float xs[4] = {v.x, v.y, v.z, v.w};
        __nv_bfloat16 hs[4], ls[4];
#pragma unroll
        for (int j = 0; j < 4; ++j) {
            hs[j] = __float2bfloat16(xs[j]);
            ls[j] = __float2bfloat16(xs[j] - __bfloat162float(hs[j]));
        }
        __nv_bfloat162 h0; h0.x = hs[0]; h0.y = hs[1];
        __nv_bfloat162 h1; h1.x = hs[2]; h1.y = hs[3];
        __nv_bfloat162 l0; l0.x = ls[0]; l0.y = ls[1];
        __nv_bfloat162 l1; l1.x = ls[2]; l1.y = ls[3];
        ((__nv_bfloat162*)(hi + i))[0] = h0;
        ((__nv_bfloat162*)(hi + i))[1] = h1;
        ((__nv_bfloat162*)(lo + i))[0] = l0;
        ((__nv_bfloat162*)(lo + i))[1] = l1;
    }
}

// ---------------------------------------------------------------------------
// split-bf16 tensor-core GEMM: out[m,n] = sum_k X[m,k]*W[n,k] + bias[n]
// acc += Xh*Wh + Xh*Wl + Xl*Wh  (fp32 accum via mma.sync)
// ---------------------------------------------------------------------------
__device__ __forceinline__ void load_tile32(uint32_t sdst,
                                            const __nv_bfloat16* __restrict__ g,
                                            int row0, int k0)
{
    // 128 rows x 64 bytes (32 bf16), padded smem rows of 80 B, 16B cp.async
#pragma unroll
    for (int it = 0; it < 2; ++it) {
        int i = threadIdx.x + it * 256;       // 0..511
        int r = i >> 2, c = i & 3;
        uint32_t dst = sdst + (uint32_t)(r * (ROWPAD * 2) + c * 16);
        const void* src = g + (size_t)(row0 + r) * D + k0 + c * 8;
        asm volatile("cp.async.cg.shared.global [%0], [%1], 16;"
                     :: "r"(dst), "l"(src) : "memory");
    }
}

__device__ void gemm_core(const __nv_bfloat16* __restrict__ Ah,
                          const __nv_bfloat16* __restrict__ Al,
                          const __nv_bfloat16* __restrict__ Bh,
                          const __nv_bfloat16* __restrict__ Bl,
                          const float* __restrict__ bias,
                          float* __restrict__ dst, bool bhsd)
{
    extern __shared__ char smraw[];
    const uint32_t sb = smem_u32(smraw);

    const int tid  = threadIdx.x;
    const int lane = tid & 31;
    const int wid  = tid >> 5;
    const int mw   = wid & 1;        // 2 M-warps  -> 64 rows each
    const int nw   = wid >> 1;       // 4 N-warps  -> 32 cols each
    const int m0   = blockIdx.y * BM;
    const int n0   = blockIdx.x * BN;

    auto tile = [&](int buf, int t) -> uint32_t { return sb + buf * BUF_B + t * TILE_B; };

    float d[4][4][4];
#pragma unroll
    for (int i = 0; i < 4; ++i)
#pragma unroll
        for (int j = 0; j < 4; ++j)
#pragma unroll
            for (int r = 0; r < 4; ++r) d[i][j][r] = 0.f;

    // prologue: chunks 0,1
#pragma unroll
    for (int p = 0; p < 2; ++p) {
        load_tile32(tile(p, 0), Ah, m0, p * KCH);
        load_tile32(tile(p, 1), Al, m0, p * KCH);
        load_tile32(tile(p, 2), Bh, n0, p * KCH);
        load_tile32(tile(p, 3), Bl, n0, p * KCH);
        asm volatile("cp.async.commit_group;" ::: "memory");
    }

    const int rq = lane >> 2;                 // 0..7
    const int cq = (lane & 3) * 2;            // 0,2,4,6

    for (int c = 0; c < NC; ++c) {
        const int buf = c & 1;
        if (c == NC - 1) asm volatile("cp.async.wait_group 0;" ::: "memory");
        else             asm volatile("cp.async.wait_group 1;" ::: "memory");
        __syncthreads();

        const uint32_t xh = tile(buf, 0), xl = tile(buf, 1);
        const uint32_t wh = tile(buf, 2), wl = tile(buf, 3);

#pragma unroll
        for (int kk2 = 0; kk2 < 2; ++kk2) {
            const int kk = kk2 * 16;
            uint32_t bhf[4][2], blf[4][2];
#pragma unroll
            for (int j = 0; j < 4; ++j) {
                int rn = nw * 32 + j * 8 + rq;
                uint32_t off = (uint32_t)((rn * ROWPAD + kk + cq) * 2);
                bhf[j][0] = lds32(wh + off);
                bhf[j][1] = lds32(wh + off + 16);
                blf[j][0] = lds32(wl + off);
                blf[j][1] = lds32(wl + off + 16);
            }
#pragma unroll
            for (int mi = 0; mi < 4; ++mi) {
                int rm = mw * 64 + mi * 16 + rq;
                uint32_t off = (uint32_t)((rm * ROWPAD + kk + cq) * 2);
                uint32_t a0 = lds32(xh + off);
                uint32_t a1 = lds32(xh + off + 8 * ROWPAD * 2);
                uint32_t a2 = lds32(xh + off + 16);
                uint32_t a3 = lds32(xh + off + 8 * ROWPAD * 2 + 16);
#pragma unroll
                for (int j = 0; j < 4; ++j) {
                    MMA16816(d[mi][j], a0, a1, a2, a3, bhf[j][0], bhf[j][1]);
                    MMA16816(d[mi][j], a0, a1, a2, a3, blf[j][0], blf[j][1]);
                }
                a0 = lds32(xl + off);
                a1 = lds32(xl + off + 8 * ROWPAD * 2);
                a2 = lds32(xl + off + 16);
                a3 = lds32(xl + off + 8 * ROWPAD * 2 + 16);
#pragma unroll
                for (int j = 0; j < 4; ++j)
                    MMA16816(d[mi][j], a0, a1, a2, a3, bhf[j][0], bhf[j][1]);
            }
        }
        __syncthreads();
        if (c + 2 < NC) {
            load_tile32(tile(buf, 0), Ah, m0, (c + 2) * KCH);
            load_tile32(tile(buf, 1), Al, m0, (c + 2) * KCH);
            load_tile32(tile(buf, 2), Bh, n0, (c + 2) * KCH);
            load_tile32(tile(buf, 3), Bl, n0, (c + 2) * KCH);
            asm volatile("cp.async.commit_group;" ::: "memory");
        }
    }

    // epilogue
#pragma unroll
    for (int mi = 0; mi < 4; ++mi) {
#pragma unroll
        for (int j = 0; j < 4; ++j) {
            int r0 = m0 + mw * 64 + mi * 16 + rq;
            int n  = n0 + nw * 32 + j * 8 + cq;
            float b0 = bias[n], b1 = bias[n + 1];
#pragma unroll
            for (int h2 = 0; h2 < 2; ++h2) {
                int r = r0 + h2 * 8;
                float2 o;
                o.x = d[mi][j][h2 * 2 + 0] + b0;
                o.y = d[mi][j][h2 * 2 + 1] + b1;
                float* p;
                if (bhsd) {
                    int b = r >> 11, srow = r & 2047;
                    int hh = n >> 6, dd = n & 63;
                    p = dst + (((size_t)(b * H + hh) * S + srow) << 6) + dd;
                } else {
                    p = dst + (size_t)r * D + n;
                }
                *(float2*)p = o;
            }
        }
    }
}

__global__ void __launch_bounds__(256) gemm_qkv_kernel(
    const float* __restrict__ bq, const float* __restrict__ bk,
    const float* __restrict__ bv)
{
    const int z = blockIdx.z;
    const float* bias = (z == 0) ? bq : (z == 1 ? bk : bv);
    float* dst        = (z == 0) ? g_Qp : (z == 1 ? g_Kp : g_Vp);
    gemm_core(g_xh[z], g_xl[z], g_wh[z], g_wl[z], bias, dst, true);
}

__global__ void __launch_bounds__(256) gemm_out_kernel(
    const float* __restrict__ bo, float* __restrict__ out)
{
    gemm_core(g_ah, g_al, g_wh[3], g_wl[3], bo, out, false);
}

// ---------------------------------------------------------------------------
// Flash attention (fp32); epilogue emits bf16 hi/lo attn for out projection.
// ---------------------------------------------------------------------------
__global__ void __launch_bounds__(256) flash_kernel(const float* __restrict__ prev)
{
    __shared__ float Qs[64][64];
    __shared__ float KP[64][64];
    __shared__ float Vs[64][64];

    const int tid = threadIdx.x;
    const int tx  = tid & 15;
    const int ty  = tid >> 4;
    const int bh  = blockIdx.y;
    const int b   = bh >> 4;
    const int hq  = bh & 15;
    const int q0  = blockIdx.x * 64;

    const float* Qbase    = g_Qp + ((size_t)bh * S + q0) * 64;
    const float* Kbase    = g_Kp + (size_t)bh * S * 64;
    const float* Vbase    = g_Vp + (size_t)bh * S * 64;
    const float* prevBase = prev + ((size_t)bh * S + q0) * S;

#pragma unroll
    for (int it = 0; it < 4; ++it) {
        int idx = tid + it * 256;
        int r = idx >> 4, kq = (idx & 15) * 4;
        float4 a = *(const float4*)(Qbase + r * 64 + kq);
        Qs[kq + 0][r] = a.x; Qs[kq + 1][r] = a.y;
        Qs[kq + 2][r] = a.z; Qs[kq + 3][r] = a.w;
    }

    float m_i[4], l_i[4], oacc[4][4];
#pragma unroll
    for (int i = 0; i < 4; ++i) {
        m_i[i] = -3.0e38f; l_i[i] = 0.f;
#pragma unroll
        for (int j = 0; j < 4; ++j) oacc[i][j] = 0.f;
    }

    for (int t0 = 0; t0 < S; t0 += 64) {
        __syncthreads();
#pragma unroll
        for (int it = 0; it < 4; ++it) {
            int idx = tid + it * 256;
            int r = idx >> 4, kq = (idx & 15) * 4;
            float4 a = *(const float4*)(Kbase + (size_t)(t0 + r) * 64 + kq);
            KP[kq + 0][r] = a.x; KP[kq + 1][r] = a.y;
            KP[kq + 2][r] = a.z; KP[kq + 3][r] = a.w;
            float4 vv = *(const float4*)(Vbase + (size_t)(t0 + r) * 64 + kq);
            *(float4*)&Vs[r][kq] = vv;
        }
        __syncthreads();

        float p[4][4];
#pragma unroll
        for (int i = 0; i < 4; ++i)
#pragma unroll
            for (int j = 0; j < 4; ++j) p[i][j] = 0.f;
#pragma unroll
        for (int kk = 0; kk < 64; ++kk) {
            float a[4], bb[4];
            *(float4*)a  = *(const float4*)&Qs[kk][ty * 4];
            *(float4*)bb = *(const float4*)&KP[kk][tx * 4];
#pragma unroll
            for (int i = 0; i < 4; ++i)
#pragma unroll
                for (int j = 0; j < 4; ++j)
                    p[i][j] = fmaf(a[i], bb[j], p[i][j]);
        }

        const uchar4 mk = *(const uchar4*)(g_maskb + b * S + t0 + tx * 4);
#pragma unroll
        for (int i = 0; i < 4; ++i) {
            float4 pv = *(const float4*)(prevBase + (size_t)(ty * 4 + i) * S + t0 + tx * 4);
            p[i][0] = mk.x ? -1.0e30f : fmaf(p[i][0], SCALE, pv.x);
            p[i][1] = mk.y ? -1.0e30f : fmaf(p[i][1], SCALE, pv.y);
            p[i][2] = mk.z ? -1.0e30f : fmaf(p[i][2], SCALE, pv.z);
            p[i][3] = mk.w ? -1.0e30f : fmaf(p[i][3], SCALE, pv.w);
        }

#pragma unroll
        for (int i = 0; i < 4; ++i) {
            float mx = fmaxf(fmaxf(p[i][0], p[i][1]), fmaxf(p[i][2], p[i][3]));
#pragma unroll
            for (int o = 8; o; o >>= 1) mx = fmaxf(mx, __shfl_xor_sync(0xffffffffu, mx, o));
            float m_new = fmaxf(m_i[i], mx);
            float corr  = __expf(m_i[i] - m_new);
            float rs = 0.f;
#pragma unroll
            for (int j = 0; j < 4; ++j) { p[i][j] = __expf(p[i][j] - m_new); rs += p[i][j]; }
#pragma unroll
            for (int o = 8; o; o >>= 1) rs += __shfl_xor_sync(0xffffffffu, rs, o);
            l_i[i] = l_i[i] * corr + rs;
            m_i[i] = m_new;
#pragma unroll
            for (int j = 0; j < 4; ++j) oacc[i][j] *= corr;
        }

        __syncthreads();
#pragma unroll
        for (int i = 0; i < 4; ++i)
#pragma unroll
            for (int j = 0; j < 4; ++j)
                KP[tx * 4 + j][ty * 4 + i] = p[i][j];
        __syncthreads();

#pragma unroll
        for (int cc = 0; cc < 64; ++cc) {
            float a[4], bb[4];
            *(float4*)a  = *(const float4*)&KP[cc][ty * 4];
            *(float4*)bb = *(const float4*)&Vs[cc][tx * 4];
#pragma unroll
            for (int i = 0; i < 4; ++i)
#pragma unroll
                for (int j = 0; j < 4; ++j)
                    oacc[i][j] = fmaf(a[i], bb[j], oacc[i][j]);
        }
    }

    // epilogue: attn -> bf16 hi/lo
#pragma unroll
    for (int i = 0; i < 4; ++i) {
        float inv = 1.0f / fmaxf(l_i[i], 1e-30f);
        int s = q0 + ty * 4 + i;
        size_t base = ((size_t)b * S + s) * 1024 + hq * 64 + tx * 4;
        __nv_bfloat16 hs[4], ls[4];
#pragma unroll
        for (int j = 0; j < 4; ++j) {
            float x = oacc[i][j] * inv;
            hs[j] = __float2bfloat16(x);
            ls[j] = __float2bfloat16(x - __bfloat162float(hs[j]));
        }
        __nv_bfloat162 h0; h0.x = hs[0]; h0.y = hs[1];
        __nv_bfloat162 h1; h1.x = hs[2]; h1.y = hs[3];
        __nv_bfloat162 l0; l0.x = ls[0]; l0.y = ls[1];
        __nv_bfloat162 l1; l1.x = ls[2]; l1.y = ls[3];
        ((__nv_bfloat162*)(g_ah + base))[0] = h0;
        ((__nv_bfloat162*)(g_ah + base))[1] = h1;
        ((__nv_bfloat162*)(g_al + base))[0] = l0;
        ((__nv_bfloat162*)(g_al + base))[1] = l1;
    }
}

// ---------------------------------------------------------------------------
// Inputs: 0:q 1:k 2:v 3:prev 4:mask 5:Wq 6:bq 7:Wk 8:bk 9:Wv 10:bv 11:Wo 12:bo
// ---------------------------------------------------------------------------
extern "C" void kernel_launch(void* const* d_in, const int* in_sizes, int n_in,
                              void* d_out, int out_size)
{
    (void)in_sizes; (void)n_in; (void)out_size;

    const float* q    = (const float*)d_in[0];
    const float* kk   = (const float*)d_in[1];
    const float* v    = (const float*)d_in[2];
    const float* prev = (const float*)d_in[3];
    const unsigned char* mask = (const unsigned char*)d_in[4];
    const float* Wq = (const float*)d_in[5];
    const float* bq = (const float*)d_in[6];
    const float* Wk = (const float*)d_in[7];
    const float* bk = (const float*)d_in[8];
    const float* Wv = (const float*)d_in[9];
    const float* bv = (const float*)d_in[10];
    const float* Wo = (const float*)d_in[11];
    const float* bo = (const float*)d_in[12];
    float* out = (float*)d_out;

    cudaFuncSetAttribute(gemm_qkv_kernel,
                         cudaFuncAttributeMaxDynamicSharedMemorySize, SMEM_DYN);
    cudaFuncSetAttribute(gemm_out_kernel,
                         cudaFuncAttributeMaxDynamicSharedMemorySize, SMEM_DYN);

    mask_prepare_kernel<<<1, 256>>>(mask);

    const int nX = M * D, nW = D * D;
    split_kernel<<<nX / 4 / 256, 256>>>(q,  0, nX);
    split_kernel<<<nX / 4 / 256, 256>>>(kk, 1, nX);
    split_kernel<<<nX / 4 / 256, 256>>>(v,  2, nX);
    split_kernel<<<nW / 4 / 256, 256>>>(Wq, 3, nW);
    split_kernel<<<nW / 4 / 256, 256>>>(Wk, 4, nW);
    split_kernel<<<nW / 4 / 256, 256>>>(Wv, 5, nW);
    split_kernel<<<nW / 4 / 256, 256>>>(Wo, 6, nW);

    gemm_qkv_kernel<<<dim3(D / BN, M / BM, 3), 256, SMEM_DYN>>>(bq, bk, bv);
    flash_kernel<<<dim3(S / 64, Bb * H), 256>>>(prev);
    gemm_out_kernel<<<dim3(D / BN, M / BM), 256, SMEM_DYN>>>(bo, out);
}

// round 5
// speedup vs baseline: 2.5974x; 2.0003x over previous
#include <cuda_runtime.h>
#include <cuda_bf16.h>
#include <cstdint>
#include <cstring>

// ---------------------------------------------------------------------------
// MultiHeadAttention B=2,S=2048,D=1024,H=16,DK=DV=64
// split-bf16 mma.sync everywhere: projections + flash attention.
// ---------------------------------------------------------------------------

namespace {
constexpr int  Bb = 2, S = 2048, D = 1024, H = 16;
constexpr int  M  = Bb * S;                    // 4096
constexpr float SCALE = 0.125f;

// projection GEMM tiling (as R4)
constexpr int BM = 128, BN = 128, KCH = 32;
constexpr int NC = D / KCH;                    // 32 chunks
constexpr int ROWPAD = 40;                     // bf16 elems per smem row (80 B)
constexpr int TILE_B = 128 * ROWPAD * 2;
constexpr int BUF_B  = 4 * TILE_B;
constexpr int SMEM_GEMM = 2 * BUF_B;           // 81920 B

// flash tiling
constexpr int QT = 128, KT = 64, RP = 72;      // q tile, kv tile, padded row elems
constexpr int NT = S / KT;                     // 32 kv tiles
constexpr int QBYTES  = QT * RP * 2;           // 18432
constexpr int KVBYTES = KT * RP * 2;           // 9216
constexpr int OFF_QH = 0, OFF_QL = QBYTES;
constexpr int OFF_KV = 2 * QBYTES;             // 36864
constexpr int KVBUF  = 4 * KVBYTES;            // Kh,Kl,Vh,Vl = 36864
constexpr int OFF_MK = OFF_KV + 2 * KVBUF;     // 110592
constexpr int SMEM_FLASH = OFF_MK + 128;       // 110720
}

// ---- device scratch (allocation-free) ----
__device__ __nv_bfloat16 g_xh[3][(size_t)M * D];   // q,k,v inputs split hi
__device__ __nv_bfloat16 g_xl[3][(size_t)M * D];
__device__ __nv_bfloat16 g_wh[4][(size_t)D * D];   // Wq,Wk,Wv,Wo hi
__device__ __nv_bfloat16 g_wl[4][(size_t)D * D];
__device__ __nv_bfloat16 g_ah[(size_t)M * D];      // attn out hi
__device__ __nv_bfloat16 g_al[(size_t)M * D];
__device__ __nv_bfloat16 g_qh[(size_t)Bb * H * S * 64];  // per-head [bh][s][64]
__device__ __nv_bfloat16 g_ql[(size_t)Bb * H * S * 64];
__device__ __nv_bfloat16 g_kh[(size_t)Bb * H * S * 64];
__device__ __nv_bfloat16 g_kl[(size_t)Bb * H * S * 64];
__device__ __nv_bfloat16 g_vh[(size_t)Bb * H * S * 64];
__device__ __nv_bfloat16 g_vl[(size_t)Bb * H * S * 64];
__device__ unsigned char g_maskb[M];

// ---------------------------------------------------------------------------
// helpers
// ---------------------------------------------------------------------------
__device__ __forceinline__ uint32_t smem_u32(const void* p) {
    uint32_t a;
    asm("{ .reg .u64 t; cvta.to.shared.u64 t, %1; cvt.u32.u64 %0, t; }"
        : "=r"(a) : "l"(p));
    return a;
}
__device__ __forceinline__ uint32_t lds32(uint32_t a) {
    uint32_t v;
    asm volatile("ld.shared.b32 %0, [%1];" : "=r"(v) : "r"(a));
    return v;
}
__device__ __forceinline__ void ldsm4(uint32_t* r, uint32_t a) {
    asm volatile("ldmatrix.sync.aligned.m8n8.x4.shared.b16 {%0,%1,%2,%3}, [%4];"
                 : "=r"(r[0]), "=r"(r[1]), "=r"(r[2]), "=r"(r[3]) : "r"(a));
}
__device__ __forceinline__ void ldsm4t(uint32_t* r, uint32_t a) {
    asm volatile("ldmatrix.sync.aligned.m8n8.x4.trans.shared.b16 {%0,%1,%2,%3}, [%4];"
                 : "=r"(r[0]), "=r"(r[1]), "=r"(r[2]), "=r"(r[3]) : "r"(a));
}
__device__ __forceinline__ uint32_t b2u(__nv_bfloat162 h) {
    uint32_t u;
    memcpy(&u, &h, 4);
    return u;
}
__device__ __forceinline__ uint32_t pack_hi(float x, float y) {
    float2 f; f.x = x; f.y = y;
    return b2u(__float22bfloat162_rn(f));
}
#define MMA16816(Dv, A0, A1, A2, A3, B0, B1)                                   \
    asm volatile(                                                              \
        "mma.sync.aligned.m16n8k16.row.col.f32.bf16.bf16.f32 "                 \
        "{%0,%1,%2,%3}, {%4,%5,%6,%7}, {%8,%9}, {%0,%1,%2,%3};"                \
        : "+f"((Dv)[0]), "+f"((Dv)[1]), "+f"((Dv)[2]), "+f"((Dv)[3])           \
        : "r"(A0), "r"(A1), "r"(A2), "r"(A3), "r"(B0), "r"(B1))
#define CPA16(dst, src)                                                        \
    asm volatile("cp.async.cg.shared.global [%0], [%1], 16;"                   \
                 :: "r"(dst), "l"(src) : "memory")

// ---------------------------------------------------------------------------
// Mask normalization (sniff bool/int32/float32 storage)
// ---------------------------------------------------------------------------
__global__ void mask_prepare_kernel(const unsigned char* __restrict__ raw)
{
    __shared__ int flags;
    if (threadIdx.x == 0) flags = 0;
    __syncthreads();
    int f = 0;
    for (int i = threadIdx.x; i < M; i += blockDim.x) {
        unsigned char c = raw[i];
        if ((i & 3) != 0 && c != 0) f |= 1;
        if ((i & 3) == 3 && c == 0x3F) f |= 2;
    }
    if (f) atomicOr(&flags, f);
    __syncthreads();
    const int fl = flags;
    for (int i = threadIdx.x; i < M; i += blockDim.x) {
        unsigned char v;
        if (fl & 2)      v = (((const float*)raw)[i] != 0.0f);
        else if (fl & 1) v = (raw[i] != 0);
        else             v = (((const int*)raw)[i] != 0);
        g_maskb[i] = v;
    }
}

// ---------------------------------------------------------------------------
// fp32 -> bf16 hi/lo split. which: 0..2 -> g_xh/g_xl, 3..6 -> g_wh/g_wl
// ---------------------------------------------------------------------------
__global__ void __launch_bounds__(256) split_kernel(
    const float* __restrict__ src, int which, int n)
{
    __nv_bfloat16 *hi, *lo;
    if (which < 3) { hi = g_xh[which];     lo = g_xl[which];     }
    else           { hi = g_wh[which - 3]; lo = g_wl[which - 3]; }

    int i = (blockIdx.x * blockDim.x + threadIdx.x) * 4;
    if (i < n) {
        float4 v = *(const float4*)(src + i);
        float xs[4] = {v.x, v.y, v.z, v.w};
        __nv_bfloat16 hs[4], ls[4];
#pragma unroll
        for (int j = 0; j < 4; ++j) {
            hs[j] = __float2bfloat16(xs[j]);
            ls[j] = __float2bfloat16(xs[j] - __bfloat162float(hs[j]));
        }
        __nv_bfloat162 h0; h0.x = hs[0]; h0.y = hs[1];
        __nv_bfloat162 h1; h1.x = hs[2]; h1.y = hs[3];
        __nv_bfloat162 l0; l0.x = ls[0]; l0.y = ls[1];
        __nv_bfloat162 l1; l1.x = ls[2]; l1.y = ls[3];
        ((__nv_bfloat162*)(hi + i))[0] = h0;
        ((__nv_bfloat162*)(hi + i))[1] = h1;
        ((__nv_bfloat162*)(lo + i))[0] = l0;
        ((__nv_bfloat162*)(lo + i))[1] = l1;
    }
}

// ---------------------------------------------------------------------------
// split-bf16 tensor-core GEMM: acc = X@W^T (+bias). Two epilogue modes:
//   mode 0: fp32 dst[m][D]           (final out-projection)
//   mode 1: bf16 hi/lo per-head [bh][s][64], value=(acc+bias)*scale
// ---------------------------------------------------------------------------
__device__ __forceinline__ void load_tile32(uint32_t sdst,
                                            const __nv_bfloat16* __restrict__ g,
                                            int row0, int k0)
{
#pragma unroll
    for (int it = 0; it < 2; ++it) {
        int i = threadIdx.x + it * 256;
        int r = i >> 2, c = i & 3;
        uint32_t dst = sdst + (uint32_t)(r * (ROWPAD * 2) + c * 16);
        const void* src = g + (size_t)(row0 + r) * D + k0 + c * 8;
        CPA16(dst, src);
    }
}

__device__ void gemm_core(const __nv_bfloat16* __restrict__ Ah,
                          const __nv_bfloat16* __restrict__ Al,
                          const __nv_bfloat16* __restrict__ Bh,
                          const __nv_bfloat16* __restrict__ Bl,
                          const float* __restrict__ bias,
                          float* __restrict__ dst,
                          __nv_bfloat16* __restrict__ dsth,
                          __nv_bfloat16* __restrict__ dstl,
                          float scale, int mode)
{
    extern __shared__ char smraw[];
    const uint32_t sb = smem_u32(smraw);

    const int tid  = threadIdx.x;
    const int lane = tid & 31;
    const int wid  = tid >> 5;
    const int mw   = wid & 1;
    const int nw   = wid >> 1;
    const int m0   = blockIdx.y * BM;
    const int n0   = blockIdx.x * BN;

    auto tile = [&](int buf, int t) -> uint32_t { return sb + buf * BUF_B + t * TILE_B; };

    float d[4][4][4];
#pragma unroll
    for (int i = 0; i < 4; ++i)
#pragma unroll
        for (int j = 0; j < 4; ++j)
#pragma unroll
            for (int r = 0; r < 4; ++r) d[i][j][r] = 0.f;

#pragma unroll
    for (int p = 0; p < 2; ++p) {
        load_tile32(tile(p, 0), Ah, m0, p * KCH);
        load_tile32(tile(p, 1), Al, m0, p * KCH);
        load_tile32(tile(p, 2), Bh, n0, p * KCH);
        load_tile32(tile(p, 3), Bl, n0, p * KCH);
        asm volatile("cp.async.commit_group;" ::: "memory");
    }

    const int rq = lane >> 2;
    const int cq = (lane & 3) * 2;

    for (int c = 0; c < NC; ++c) {
        const int buf = c & 1;
        if (c == NC - 1) asm volatile("cp.async.wait_group 0;" ::: "memory");
        else             asm volatile("cp.async.wait_group 1;" ::: "memory");
        __syncthreads();

        const uint32_t xh = tile(buf, 0), xl = tile(buf, 1);
        const uint32_t wh = tile(buf, 2), wl = tile(buf, 3);

#pragma unroll
        for (int kk2 = 0; kk2 < 2; ++kk2) {
            const int kk = kk2 * 16;
            uint32_t bhf[4][2], blf[4][2];
#pragma unroll
            for (int j = 0; j < 4; ++j) {
                int rn = nw * 32 + j * 8 + rq;
                uint32_t off = (uint32_t)((rn * ROWPAD + kk + cq) * 2);
                bhf[j][0] = lds32(wh + off);
                bhf[j][1] = lds32(wh + off + 16);
                blf[j][0] = lds32(wl + off);
                blf[j][1] = lds32(wl + off + 16);
            }
#pragma unroll
            for (int mi = 0; mi < 4; ++mi) {
                int rm = mw * 64 + mi * 16 + rq;
                uint32_t off = (uint32_t)((rm * ROWPAD + kk + cq) * 2);
                uint32_t a0 = lds32(xh + off);
                uint32_t a1 = lds32(xh + off + 8 * ROWPAD * 2);
                uint32_t a2 = lds32(xh + off + 16);
                uint32_t a3 = lds32(xh + off + 8 * ROWPAD * 2 + 16);
#pragma unroll
                for (int j = 0; j < 4; ++j) {
                    MMA16816(d[mi][j], a0, a1, a2, a3, bhf[j][0], bhf[j][1]);
                    MMA16816(d[mi][j], a0, a1, a2, a3, blf[j][0], blf[j][1]);
                }
                a0 = lds32(xl + off);
                a1 = lds32(xl + off + 8 * ROWPAD * 2);
                a2 = lds32(xl + off + 16);
                a3 = lds32(xl + off + 8 * ROWPAD * 2 + 16);
#pragma unroll
                for (int j = 0; j < 4; ++j)
                    MMA16816(d[mi][j], a0, a1, a2, a3, bhf[j][0], bhf[j][1]);
            }
        }
        __syncthreads();
        if (c + 2 < NC) {
            load_tile32(tile(buf, 0), Ah, m0, (c + 2) * KCH);
            load_tile32(tile(buf, 1), Al, m0, (c + 2) * KCH);
            load_tile32(tile(buf, 2), Bh, n0, (c + 2) * KCH);
            load_tile32(tile(buf, 3), Bl, n0, (c + 2) * KCH);
            asm volatile("cp.async.commit_group;" ::: "memory");
        }
    }

#pragma unroll
    for (int mi = 0; mi < 4; ++mi) {
#pragma unroll
        for (int j = 0; j < 4; ++j) {
            int r0 = m0 + mw * 64 + mi * 16 + rq;
            int n  = n0 + nw * 32 + j * 8 + cq;
            float b0 = bias[n], b1 = bias[n + 1];
#pragma unroll
            for (int h2 = 0; h2 < 2; ++h2) {
                int r = r0 + h2 * 8;
                float v0 = d[mi][j][h2 * 2 + 0] + b0;
                float v1 = d[mi][j][h2 * 2 + 1] + b1;
                if (mode == 0) {
                    float2 o; o.x = v0; o.y = v1;
                    *(float2*)(dst + (size_t)r * D + n) = o;
                } else {
                    v0 *= scale; v1 *= scale;
                    int b = r >> 11, srow = r & 2047;
                    int hh = n >> 6, dd = n & 63;
                    size_t base = (((size_t)(b * H + hh) * S + srow) << 6) + dd;
                    __nv_bfloat16 h0 = __float2bfloat16(v0);
                    __nv_bfloat16 h1 = __float2bfloat16(v1);
                    __nv_bfloat162 hp; hp.x = h0; hp.y = h1;
                    __nv_bfloat162 lp;
                    lp.x = __float2bfloat16(v0 - __bfloat162float(h0));
                    lp.y = __float2bfloat16(v1 - __bfloat162float(h1));
                    *(uint32_t*)(dsth + base) = b2u(hp);
                    *(uint32_t*)(dstl + base) = b2u(lp);
                }
            }
        }
    }
}

__global__ void __launch_bounds__(256) gemm_qkv_kernel(
    const float* __restrict__ bq, const float* __restrict__ bk,
    const float* __restrict__ bv)
{
    const int z = blockIdx.z;
    const float* bias = (z == 0) ? bq : (z == 1 ? bk : bv);
    __nv_bfloat16* dh = (z == 0) ? g_qh : (z == 1 ? g_kh : g_vh);
    __nv_bfloat16* dl = (z == 0) ? g_ql : (z == 1 ? g_kl : g_vl);
    float scale = (z == 0) ? SCALE : 1.0f;
    gemm_core(g_xh[z], g_xl[z], g_wh[z], g_wl[z], bias,
              nullptr, dh, dl, scale, 1);
}

__global__ void __launch_bounds__(256) gemm_out_kernel(
    const float* __restrict__ bo, float* __restrict__ out)
{
    gemm_core(g_ah, g_al, g_wh[3], g_wl[3], bo, out, nullptr, nullptr, 1.0f, 0);
}

// ---------------------------------------------------------------------------
// Flash attention, split-bf16 mma.sync. q-tile 128, kv-tile 64, 8 warps.
// ---------------------------------------------------------------------------
__global__ void __launch_bounds__(256) flash_kernel(const float* __restrict__ prev)
{
    extern __shared__ char sm[];
    const uint32_t sb = smem_u32(sm);

    const int tid  = threadIdx.x;
    const int lane = tid & 31;
    const int w    = tid >> 5;
    const int bh   = blockIdx.y;
    const int b    = bh >> 4;
    const int hq   = bh & 15;
    const int q0   = blockIdx.x * QT;
    const int rq   = lane >> 2;
    const int cq   = (lane & 3) * 2;
    const int mrow = w * 16;

    const __nv_bfloat16* Qhg = g_qh + ((size_t)bh * S + q0) * 64;
    const __nv_bfloat16* Qlg = g_ql + ((size_t)bh * S + q0) * 64;
    const __nv_bfloat16* Khg = g_kh + (size_t)bh * S * 64;
    const __nv_bfloat16* Klg = g_kl + (size_t)bh * S * 64;
    const __nv_bfloat16* Vhg = g_vh + (size_t)bh * S * 64;
    const __nv_bfloat16* Vlg = g_vl + (size_t)bh * S * 64;

    // Q tiles (hi/lo) -> smem
#pragma unroll
    for (int it = 0; it < 8; ++it) {
        int i = tid + it * 256;
        int arr = i >> 10, r = (i >> 3) & 127, c = i & 7;
        const __nv_bfloat16* src = (arr ? Qlg : Qhg) + (size_t)r * 64 + c * 8;
        uint32_t dst = sb + (arr ? OFF_QL : OFF_QH) + (uint32_t)(r * (RP * 2) + c * 16);
        CPA16(dst, src);
    }

    auto load_kv = [&](int t, int buf) {
#pragma unroll
        for (int it = 0; it < 8; ++it) {
            int i = tid + it * 256;
            int arr = i >> 9, r = (i >> 3) & 63, c = i & 7;
            const __nv_bfloat16* base = (arr == 0) ? Khg : (arr == 1) ? Klg
                                      : (arr == 2) ? Vhg : Vlg;
            const __nv_bfloat16* src = base + (size_t)(t * KT + r) * 64 + c * 8;
            uint32_t dst = sb + OFF_KV + buf * KVBUF + arr * KVBYTES
                         + (uint32_t)(r * (RP * 2) + c * 16);
            CPA16(dst, src);
        }
        if (tid < 16) {
            uint32_t mv = *(const uint32_t*)(g_maskb + b * S + t * KT + tid * 4);
            *(uint32_t*)(sm + OFF_MK + buf * 64 + tid * 4) = mv;
        }
    };

    load_kv(0, 0);
    asm volatile("cp.async.commit_group;" ::: "memory");   // group: Q + kv0
    load_kv(1, 1);
    asm volatile("cp.async.commit_group;" ::: "memory");

    float m_i[2] = {-3.0e38f, -3.0e38f};
    float l_i[2] = {0.f, 0.f};
    float o[8][4];
#pragma unroll
    for (int j = 0; j < 8; ++j)
#pragma unroll
        for (int r = 0; r < 4; ++r) o[j][r] = 0.f;

    const float* prow0 = prev + ((size_t)bh * S + q0 + mrow + rq) * S;
    const float* prow1 = prow0 + (size_t)8 * S;

    for (int t = 0; t < NT; ++t) {
        const int buf = t & 1;
        if (t == NT - 1) asm volatile("cp.async.wait_group 0;" ::: "memory");
        else             asm volatile("cp.async.wait_group 1;" ::: "memory");
        __syncthreads();

        const uint32_t KH = sb + OFF_KV + buf * KVBUF;
        const uint32_t KL = KH + KVBYTES;
        const uint32_t VH = KL + KVBYTES;
        const uint32_t VL = VH + KVBYTES;
        const uint32_t QH = sb + OFF_QH, QL = sb + OFF_QL;

        // --- QK^T (split: QhKh + QhKl + QlKh) ---
        float s[8][4];
#pragma unroll
        for (int j = 0; j < 8; ++j)
#pragma unroll
            for (int r = 0; r < 4; ++r) s[j][r] = 0.f;

#pragma unroll
        for (int kc = 0; kc < 4; ++kc) {
            uint32_t aoff = (uint32_t)((mrow + (lane & 15)) * (RP * 2)
                                       + kc * 32 + (lane >> 4) * 16);
            uint32_t ah[4], al[4];
            ldsm4(ah, QH + aoff);
            ldsm4(al, QL + aoff);
#pragma unroll
            for (int jp = 0; jp < 4; ++jp) {
                uint32_t boff = (uint32_t)(((jp * 2 + (lane >> 4)) * 8 + (lane & 7)) * (RP * 2)
                                           + kc * 32 + ((lane >> 3) & 1) * 16);
                uint32_t bh4[4], bl4[4];
                ldsm4(bh4, KH + boff);
                ldsm4(bl4, KL + boff);
                MMA16816(s[2 * jp],     ah[0], ah[1], ah[2], ah[3], bh4[0], bh4[1]);
                MMA16816(s[2 * jp],     al[0], al[1], al[2], al[3], bh4[0], bh4[1]);
                MMA16816(s[2 * jp],     ah[0], ah[1], ah[2], ah[3], bl4[0], bl4[1]);
                MMA16816(s[2 * jp + 1], ah[0], ah[1], ah[2], ah[3], bh4[2], bh4[3]);
                MMA16816(s[2 * jp + 1], al[0], al[1], al[2], al[3], bh4[2], bh4[3]);
                MMA16816(s[2 * jp + 1], ah[0], ah[1], ah[2], ah[3], bl4[2], bl4[3]);
            }
        }

        // --- + prev, mask ---
#pragma unroll
        for (int j = 0; j < 8; ++j) {
            const unsigned char* mkp = (const unsigned char*)(sm + OFF_MK + buf * 64 + j * 8 + cq);
            unsigned char mk0 = mkp[0], mk1 = mkp[1];
            float2 p0 = *(const float2*)(prow0 + (size_t)t * KT + j * 8 + cq);
            float2 p1 = *(const float2*)(prow1 + (size_t)t * KT + j * 8 + cq);
            s[j][0] = mk0 ? -1.0e30f : s[j][0] + p0.x;
            s[j][1] = mk1 ? -1.0e30f : s[j][1] + p0.y;
            s[j][2] = mk0 ? -1.0e30f : s[j][2] + p1.x;
            s[j][3] = mk1 ? -1.0e30f : s[j][3] + p1.y;
        }

        // --- online softmax (rows rq, rq+8) ---
#pragma unroll
        for (int r = 0; r < 2; ++r) {
            float mx = -3.0e38f;
#pragma unroll
            for (int j = 0; j < 8; ++j)
                mx = fmaxf(mx, fmaxf(s[j][2 * r], s[j][2 * r + 1]));
            mx = fmaxf(mx, __shfl_xor_sync(0xffffffffu, mx, 1));
            mx = fmaxf(mx, __shfl_xor_sync(0xffffffffu, mx, 2));
            float m_new = fmaxf(m_i[r], mx);
            float corr  = __expf(m_i[r] - m_new);
            float rs = 0.f;
#pragma unroll
            for (int j = 0; j < 8; ++j) {
                s[j][2 * r]     = __expf(s[j][2 * r]     - m_new);
                s[j][2 * r + 1] = __expf(s[j][2 * r + 1] - m_new);
                rs += s[j][2 * r] + s[j][2 * r + 1];
            }
            rs += __shfl_xor_sync(0xffffffffu, rs, 1);
            rs += __shfl_xor_sync(0xffffffffu, rs, 2);
            l_i[r] = l_i[r] * corr + rs;
            m_i[r] = m_new;
#pragma unroll
            for (int j = 0; j < 8; ++j) {
                o[j][2 * r]     *= corr;
                o[j][2 * r + 1] *= corr;
            }
        }

        // --- P@V (split: PhVh + PlVh + PhVl), P direct from registers ---
#pragma unroll
        for (int kc2 = 0; kc2 < 4; ++kc2) {
            const int j0 = 2 * kc2, j1 = j0 + 1;
            uint32_t pah[4], pal[4];
#pragma unroll
            for (int q = 0; q < 4; ++q) {
                const int jt = (q & 2) ? j1 : j0;
                const int rr = (q & 1) ? 2 : 0;
                float x = s[jt][rr], y = s[jt][rr + 1];
                __nv_bfloat16 hx = __float2bfloat16(x);
                __nv_bfloat16 hy = __float2bfloat16(y);
                __nv_bfloat162 hp; hp.x = hx; hp.y = hy;
                __nv_bfloat162 lp;
                lp.x = __float2bfloat16(x - __bfloat162float(hx));
                lp.y = __float2bfloat16(y - __bfloat162float(hy));
                pah[q] = b2u(hp);
                pal[q] = b2u(lp);
            }
#pragma unroll
            for (int jp = 0; jp < 4; ++jp) {
                uint32_t voff = (uint32_t)((kc2 * 16 + ((lane >> 3) & 1) * 8 + (lane & 7)) * (RP * 2)
                                           + (jp * 2 + (lane >> 4)) * 16);
                uint32_t vh4[4], vl4[4];
                ldsm4t(vh4, VH + voff);
                ldsm4t(vl4, VL + voff);
                MMA16816(o[2 * jp],     pah[0], pah[1], pah[2], pah[3], vh4[0], vh4[1]);
                MMA16816(o[2 * jp],     pal[0], pal[1], pal[2], pal[3], vh4[0], vh4[1]);
                MMA16816(o[2 * jp],     pah[0], pah[1], pah[2], pah[3], vl4[0], vl4[1]);
                MMA16816(o[2 * jp + 1], pah[0], pah[1], pah[2], pah[3], vh4[2], vh4[3]);
                MMA16816(o[2 * jp + 1], pal[0], pal[1], pal[2], pal[3], vh4[2], vh4[3]);
                MMA16816(o[2 * jp + 1], pah[0], pah[1], pah[2], pah[3], vl4[2], vl4[3]);
            }
        }

        __syncthreads();
        if (t + 2 < NT) {
            load_kv(t + 2, buf);
            asm volatile("cp.async.commit_group;" ::: "memory");
        }
    }

    // --- epilogue: normalize, emit bf16 hi/lo attn [b][s][H*64] ---
    const float inv0 = 1.0f / fmaxf(l_i[0], 1e-30f);
    const float inv1 = 1.0f / fmaxf(l_i[1], 1e-30f);
    const size_t row0 = (size_t)b * S + q0 + mrow + rq;
#pragma unroll
    for (int jn = 0; jn < 8; ++jn) {
        const int col = hq * 64 + jn * 8 + cq;
        float v0 = o[jn][0] * inv0, v1 = o[jn][1] * inv0;
        float v2 = o[jn][2] * inv1, v3 = o[jn][3] * inv1;

        __nv_bfloat16 h0 = __float2bfloat16(v0), h1 = __float2bfloat16(v1);
        __nv_bfloat162 hp0; hp0.x = h0; hp0.y = h1;
        __nv_bfloat162 lp0;
        lp0.x = __float2bfloat16(v0 - __bfloat162float(h0));
        lp0.y = __float2bfloat16(v1 - __bfloat162float(h1));
        *(uint32_t*)(g_ah + row0 * 1024 + col) = b2u(hp0);
        *(uint32_t*)(g_al + row0 * 1024 + col) = b2u(lp0);

        __nv_bfloat16 h2 = __float2bfloat16(v2), h3 = __float2bfloat16(v3);
        __nv_bfloat162 hp1; hp1.x = h2; hp1.y = h3;
        __nv_bfloat162 lp1;
        lp1.x = __float2bfloat16(v2 - __bfloat162float(h2));
        lp1.y = __float2bfloat16(v3 - __bfloat162float(h3));
        *(uint32_t*)(g_ah + (row0 + 8) * 1024 + col) = b2u(hp1);
        *(uint32_t*)(g_al + (row0 + 8) * 1024 + col) = b2u(lp1);
    }
}

// ---------------------------------------------------------------------------
// Inputs: 0:q 1:k 2:v 3:prev 4:mask 5:Wq 6:bq 7:Wk 8:bk 9:Wv 10:bv 11:Wo 12:bo
// ---------------------------------------------------------------------------
extern "C" void kernel_launch(void* const* d_in, const int* in_sizes, int n_in,
                              void* d_out, int out_size)
{
    (void)in_sizes; (void)n_in; (void)out_size;

    const float* q    = (const float*)d_in[0];
    const float* kk   = (const float*)d_in[1];
    const float* v    = (const float*)d_in[2];
    const float* prev = (const float*)d_in[3];
    const unsigned char* mask = (const unsigned char*)d_in[4];
    const float* Wq = (const float*)d_in[5];
    const float* bq = (const float*)d_in[6];
    const float* Wk = (const float*)d_in[7];
    const float* bk = (const float*)d_in[8];
    const float* Wv = (const float*)d_in[9];
    const float* bv = (const float*)d_in[10];
    const float* Wo = (const float*)d_in[11];
    const float* bo = (const float*)d_in[12];
    float* out = (float*)d_out;

    cudaFuncSetAttribute(gemm_qkv_kernel,
                         cudaFuncAttributeMaxDynamicSharedMemorySize, SMEM_GEMM);
    cudaFuncSetAttribute(gemm_out_kernel,
                         cudaFuncAttributeMaxDynamicSharedMemorySize, SMEM_GEMM);
    cudaFuncSetAttribute(flash_kernel,
                         cudaFuncAttributeMaxDynamicSharedMemorySize, SMEM_FLASH);

    mask_prepare_kernel<<<1, 256>>>(mask);

    const int nX = M * D, nW = D * D;
    split_kernel<<<nX / 4 / 256, 256>>>(q,  0, nX);
    split_kernel<<<nX / 4 / 256, 256>>>(kk, 1, nX);
    split_kernel<<<nX / 4 / 256, 256>>>(v,  2, nX);
    split_kernel<<<nW / 4 / 256, 256>>>(Wq, 3, nW);
    split_kernel<<<nW / 4 / 256, 256>>>(Wk, 4, nW);
    split_kernel<<<nW / 4 / 256, 256>>>(Wv, 5, nW);
    split_kernel<<<nW / 4 / 256, 256>>>(Wo, 6, nW);

    gemm_qkv_kernel<<<dim3(D / BN, M / BM, 3), 256, SMEM_GEMM>>>(bq, bk, bv);
    flash_kernel<<<dim3(S / QT, Bb * H), 256, SMEM_FLASH>>>(prev);
    gemm_out_kernel<<<dim3(D / BN, M / BM), 256, SMEM_GEMM>>>(bo, out);
}

// round 6
// speedup vs baseline: 2.8329x; 1.0906x over previous
#include <cuda_runtime.h>
#include <cuda_bf16.h>
#include <cstdint>
#include <cstring>

// ---------------------------------------------------------------------------
// MultiHeadAttention B=2,S=2048,D=1024,H=16,DK=DV=64
// split-bf16 mma.sync everywhere: projections + flash attention.
// R6: flash at 2 CTAs/SM (launch_bounds(256,2)), fused split kernels.
// ---------------------------------------------------------------------------

namespace {
constexpr int  Bb = 2, S = 2048, D = 1024, H = 16;
constexpr int  M  = Bb * S;                    // 4096
constexpr float SCALE = 0.125f;

// projection GEMM tiling
constexpr int BM = 128, BN = 128, KCH = 32;
constexpr int NC = D / KCH;                    // 32 chunks
constexpr int ROWPAD = 40;                     // bf16 elems per smem row (80 B)
constexpr int TILE_B = 128 * ROWPAD * 2;
constexpr int BUF_B  = 4 * TILE_B;
constexpr int SMEM_GEMM = 2 * BUF_B;           // 81920 B

// flash tiling
constexpr int QT = 128, KT = 64, RP = 72;      // q tile, kv tile, padded row elems
constexpr int NT = S / KT;                     // 32 kv tiles
constexpr int QBYTES  = QT * RP * 2;           // 18432
constexpr int KVBYTES = KT * RP * 2;           // 9216
constexpr int OFF_QH = 0, OFF_QL = QBYTES;
constexpr int OFF_KV = 2 * QBYTES;             // 36864
constexpr int KVBUF  = 4 * KVBYTES;            // Kh,Kl,Vh,Vl = 36864
constexpr int OFF_MK = OFF_KV + 2 * KVBUF;     // 110592
constexpr int SMEM_FLASH = OFF_MK + 128;       // 110720
}

// ---- device scratch (allocation-free) ----
__device__ __nv_bfloat16 g_xh[3][(size_t)M * D];   // q,k,v inputs split hi
__device__ __nv_bfloat16 g_xl[3][(size_t)M * D];
__device__ __nv_bfloat16 g_wh[4][(size_t)D * D];   // Wq,Wk,Wv,Wo hi
__device__ __nv_bfloat16 g_wl[4][(size_t)D * D];
__device__ __nv_bfloat16 g_ah[(size_t)M * D];      // attn out hi
__device__ __nv_bfloat16 g_al[(size_t)M * D];
__device__ __nv_bfloat16 g_qh[(size_t)Bb * H * S * 64];  // per-head [bh][s][64]
__device__ __nv_bfloat16 g_ql[(size_t)Bb * H * S * 64];
__device__ __nv_bfloat16 g_kh[(size_t)Bb * H * S * 64];
__device__ __nv_bfloat16 g_kl[(size_t)Bb * H * S * 64];
__device__ __nv_bfloat16 g_vh[(size_t)Bb * H * S * 64];
__device__ __nv_bfloat16 g_vl[(size_t)Bb * H * S * 64];
__device__ unsigned char g_maskb[M];

// ---------------------------------------------------------------------------
// helpers
// ---------------------------------------------------------------------------
__device__ __forceinline__ uint32_t smem_u32(const void* p) {
    uint32_t a;
    asm("{ .reg .u64 t; cvta.to.shared.u64 t, %1; cvt.u32.u64 %0, t; }"
        : "=r"(a) : "l"(p));
    return a;
}
__device__ __forceinline__ uint32_t lds32(uint32_t a) {
    uint32_t v;
    asm volatile("ld.shared.b32 %0, [%1];" : "=r"(v) : "r"(a));
    return v;
}
__device__ __forceinline__ void ldsm4(uint32_t* r, uint32_t a) {
    asm volatile("ldmatrix.sync.aligned.m8n8.x4.shared.b16 {%0,%1,%2,%3}, [%4];"
                 : "=r"(r[0]), "=r"(r[1]), "=r"(r[2]), "=r"(r[3]) : "r"(a));
}
__device__ __forceinline__ void ldsm4t(uint32_t* r, uint32_t a) {
    asm volatile("ldmatrix.sync.aligned.m8n8.x4.trans.shared.b16 {%0,%1,%2,%3}, [%4];"
                 : "=r"(r[0]), "=r"(r[1]), "=r"(r[2]), "=r"(r[3]) : "r"(a));
}
__device__ __forceinline__ uint32_t b2u(__nv_bfloat162 h) {
    uint32_t u;
    memcpy(&u, &h, 4);
    return u;
}
#define MMA16816(Dv, A0, A1, A2, A3, B0, B1)                                   \
    asm volatile(                                                              \
        "mma.sync.aligned.m16n8k16.row.col.f32.bf16.bf16.f32 "                 \
        "{%0,%1,%2,%3}, {%4,%5,%6,%7}, {%8,%9}, {%0,%1,%2,%3};"                \
        : "+f"((Dv)[0]), "+f"((Dv)[1]), "+f"((Dv)[2]), "+f"((Dv)[3])           \
        : "r"(A0), "r"(A1), "r"(A2), "r"(A3), "r"(B0), "r"(B1))
#define CPA16(dst, src)                                                        \
    asm volatile("cp.async.cg.shared.global [%0], [%1], 16;"                   \
                 :: "r"(dst), "l"(src) : "memory")

// ---------------------------------------------------------------------------
// Mask normalization (sniff bool/int32/float32 storage)
// ---------------------------------------------------------------------------
__global__ void mask_prepare_kernel(const unsigned char* __restrict__ raw)
{
    __shared__ int flags;
    if (threadIdx.x == 0) flags = 0;
    __syncthreads();
    int f = 0;
    for (int i = threadIdx.x; i < M; i += blockDim.x) {
        unsigned char c = raw[i];
        if ((i & 3) != 0 && c != 0) f |= 1;
        if ((i & 3) == 3 && c == 0x3F) f |= 2;
    }
    if (f) atomicOr(&flags, f);
    __syncthreads();
    const int fl = flags;
    for (int i = threadIdx.x; i < M; i += blockDim.x) {
        unsigned char v;
        if (fl & 2)      v = (((const float*)raw)[i] != 0.0f);
        else if (fl & 1) v = (raw[i] != 0);
        else             v = (((const int*)raw)[i] != 0);
        g_maskb[i] = v;
    }
}

// ---------------------------------------------------------------------------
// Fused fp32 -> bf16 hi/lo splits. One launch for q,k,v (z=0..2, 8 floats per
// thread), one for the four weights (z=0..3).
// ---------------------------------------------------------------------------
__device__ __forceinline__ void split8(const float* __restrict__ src,
                                       __nv_bfloat16* __restrict__ hi,
                                       __nv_bfloat16* __restrict__ lo,
                                       int i)
{
#pragma unroll
    for (int half = 0; half < 2; ++half) {
        float4 v = *(const float4*)(src + i + half * 4);
        float xs[4] = {v.x, v.y, v.z, v.w};
        __nv_bfloat16 hs[4], ls[4];
#pragma unroll
        for (int j = 0; j < 4; ++j) {
            hs[j] = __float2bfloat16(xs[j]);
            ls[j] = __float2bfloat16(xs[j] - __bfloat162float(hs[j]));
        }
        __nv_bfloat162 h0; h0.x = hs[0]; h0.y = hs[1];
        __nv_bfloat162 h1; h1.x = hs[2]; h1.y = hs[3];
        __nv_bfloat162 l0; l0.x = ls[0]; l0.y = ls[1];
        __nv_bfloat162 l1; l1.x = ls[2]; l1.y = ls[3];
        ((__nv_bfloat162*)(hi + i + half * 4))[0] = h0;
        ((__nv_bfloat162*)(hi + i + half * 4))[1] = h1;
        ((__nv_bfloat162*)(lo + i + half * 4))[0] = l0;
        ((__nv_bfloat162*)(lo + i + half * 4))[1] = l1;
    }
}

__global__ void __launch_bounds__(256) split_x_kernel(
    const float* __restrict__ q, const float* __restrict__ k,
    const float* __restrict__ v)
{
    const int z = blockIdx.z;
    const float* src = (z == 0) ? q : (z == 1 ? k : v);
    int i = (blockIdx.x * blockDim.x + threadIdx.x) * 8;
    split8(src, g_xh[z], g_xl[z], i);
}

__global__ void __launch_bounds__(256) split_w_kernel(
    const float* __restrict__ Wq, const float* __restrict__ Wk,
    const float* __restrict__ Wv, const float* __restrict__ Wo)
{
    const int z = blockIdx.z;
    const float* src = (z == 0) ? Wq : (z == 1 ? Wk : (z == 2 ? Wv : Wo));
    int i = (blockIdx.x * blockDim.x + threadIdx.x) * 8;
    split8(src, g_wh[z], g_wl[z], i);
}

// ---------------------------------------------------------------------------
// split-bf16 tensor-core GEMM: acc = X@W^T (+bias). Two epilogue modes:
//   mode 0: fp32 dst[m][D]           (final out-projection)
//   mode 1: bf16 hi/lo per-head [bh][s][64], value=(acc+bias)*scale
// ---------------------------------------------------------------------------
__device__ __forceinline__ void load_tile32(uint32_t sdst,
                                            const __nv_bfloat16* __restrict__ g,
                                            int row0, int k0)
{
#pragma unroll
    for (int it = 0; it < 2; ++it) {
        int i = threadIdx.x + it * 256;
        int r = i >> 2, c = i & 3;
        uint32_t dst = sdst + (uint32_t)(r * (ROWPAD * 2) + c * 16);
        const void* src = g + (size_t)(row0 + r) * D + k0 + c * 8;
        CPA16(dst, src);
    }
}

__device__ void gemm_core(const __nv_bfloat16* __restrict__ Ah,
                          const __nv_bfloat16* __restrict__ Al,
                          const __nv_bfloat16* __restrict__ Bh,
                          const __nv_bfloat16* __restrict__ Bl,
                          const float* __restrict__ bias,
                          float* __restrict__ dst,
                          __nv_bfloat16* __restrict__ dsth,
                          __nv_bfloat16* __restrict__ dstl,
                          float scale, int mode)
{
    extern __shared__ char smraw[];
    const uint32_t sb = smem_u32(smraw);

    const int tid  = threadIdx.x;
    const int lane = tid & 31;
    const int wid  = tid >> 5;
    const int mw   = wid & 1;
    const int nw   = wid >> 1;
    const int m0   = blockIdx.y * BM;
    const int n0   = blockIdx.x * BN;

    auto tile = [&](int buf, int t) -> uint32_t { return sb + buf * BUF_B + t * TILE_B; };

    float d[4][4][4];
#pragma unroll
    for (int i = 0; i < 4; ++i)
#pragma unroll
        for (int j = 0; j < 4; ++j)
#pragma unroll
            for (int r = 0; r < 4; ++r) d[i][j][r] = 0.f;

#pragma unroll
    for (int p = 0; p < 2; ++p) {
        load_tile32(tile(p, 0), Ah, m0, p * KCH);
        load_tile32(tile(p, 1), Al, m0, p * KCH);
        load_tile32(tile(p, 2), Bh, n0, p * KCH);
        load_tile32(tile(p, 3), Bl, n0, p * KCH);
        asm volatile("cp.async.commit_group;" ::: "memory");
    }

    const int rq = lane >> 2;
    const int cq = (lane & 3) * 2;

    for (int c = 0; c < NC; ++c) {
        const int buf = c & 1;
        if (c == NC - 1) asm volatile("cp.async.wait_group 0;" ::: "memory");
        else             asm volatile("cp.async.wait_group 1;" ::: "memory");
        __syncthreads();

        const uint32_t xh = tile(buf, 0), xl = tile(buf, 1);
        const uint32_t wh = tile(buf, 2), wl = tile(buf, 3);

#pragma unroll
        for (int kk2 = 0; kk2 < 2; ++kk2) {
            const int kk = kk2 * 16;
            uint32_t bhf[4][2], blf[4][2];
#pragma unroll
            for (int j = 0; j < 4; ++j) {
                int rn = nw * 32 + j * 8 + rq;
                uint32_t off = (uint32_t)((rn * ROWPAD + kk + cq) * 2);
                bhf[j][0] = lds32(wh + off);
                bhf[j][1] = lds32(wh + off + 16);
                blf[j][0] = lds32(wl + off);
                blf[j][1] = lds32(wl + off + 16);
            }
#pragma unroll
            for (int mi = 0; mi < 4; ++mi) {
                int rm = mw * 64 + mi * 16 + rq;
                uint32_t off = (uint32_t)((rm * ROWPAD + kk + cq) * 2);
                uint32_t a0 = lds32(xh + off);
                uint32_t a1 = lds32(xh + off + 8 * ROWPAD * 2);
                uint32_t a2 = lds32(xh + off + 16);
                uint32_t a3 = lds32(xh + off + 8 * ROWPAD * 2 + 16);
#pragma unroll
                for (int j = 0; j < 4; ++j) {
                    MMA16816(d[mi][j], a0, a1, a2, a3, bhf[j][0], bhf[j][1]);
                    MMA16816(d[mi][j], a0, a1, a2, a3, blf[j][0], blf[j][1]);
                }
                a0 = lds32(xl + off);
                a1 = lds32(xl + off + 8 * ROWPAD * 2);
                a2 = lds32(xl + off + 16);
                a3 = lds32(xl + off + 8 * ROWPAD * 2 + 16);
#pragma unroll
                for (int j = 0; j < 4; ++j)
                    MMA16816(d[mi][j], a0, a1, a2, a3, bhf[j][0], bhf[j][1]);
            }
        }
        __syncthreads();
        if (c + 2 < NC) {
            load_tile32(tile(buf, 0), Ah, m0, (c + 2) * KCH);
            load_tile32(tile(buf, 1), Al, m0, (c + 2) * KCH);
            load_tile32(tile(buf, 2), Bh, n0, (c + 2) * KCH);
            load_tile32(tile(buf, 3), Bl, n0, (c + 2) * KCH);
            asm volatile("cp.async.commit_group;" ::: "memory");
        }
    }

#pragma unroll
    for (int mi = 0; mi < 4; ++mi) {
#pragma unroll
        for (int j = 0; j < 4; ++j) {
            int r0 = m0 + mw * 64 + mi * 16 + rq;
            int n  = n0 + nw * 32 + j * 8 + cq;
            float b0 = bias[n], b1 = bias[n + 1];
#pragma unroll
            for (int h2 = 0; h2 < 2; ++h2) {
                int r = r0 + h2 * 8;
                float v0 = d[mi][j][h2 * 2 + 0] + b0;
                float v1 = d[mi][j][h2 * 2 + 1] + b1;
                if (mode == 0) {
                    float2 o; o.x = v0; o.y = v1;
                    *(float2*)(dst + (size_t)r * D + n) = o;
                } else {
                    v0 *= scale; v1 *= scale;
                    int b = r >> 11, srow = r & 2047;
                    int hh = n >> 6, dd = n & 63;
                    size_t base = (((size_t)(b * H + hh) * S + srow) << 6) + dd;
                    __nv_bfloat16 h0 = __float2bfloat16(v0);
                    __nv_bfloat16 h1 = __float2bfloat16(v1);
                    __nv_bfloat162 hp; hp.x = h0; hp.y = h1;
                    __nv_bfloat162 lp;
                    lp.x = __float2bfloat16(v0 - __bfloat162float(h0));
                    lp.y = __float2bfloat16(v1 - __bfloat162float(h1));
                    *(uint32_t*)(dsth + base) = b2u(hp);
                    *(uint32_t*)(dstl + base) = b2u(lp);
                }
            }
        }
    }
}

__global__ void __launch_bounds__(256) gemm_qkv_kernel(
    const float* __restrict__ bq, const float* __restrict__ bk,
    const float* __restrict__ bv)
{
    const int z = blockIdx.z;
    const float* bias = (z == 0) ? bq : (z == 1 ? bk : bv);
    __nv_bfloat16* dh = (z == 0) ? g_qh : (z == 1 ? g_kh : g_vh);
    __nv_bfloat16* dl = (z == 0) ? g_ql : (z == 1 ? g_kl : g_vl);
    float scale = (z == 0) ? SCALE : 1.0f;
    gemm_core(g_xh[z], g_xl[z], g_wh[z], g_wl[z], bias,
              nullptr, dh, dl, scale, 1);
}

__global__ void __launch_bounds__(256) gemm_out_kernel(
    const float* __restrict__ bo, float* __restrict__ out)
{
    gemm_core(g_ah, g_al, g_wh[3], g_wl[3], bo, out, nullptr, nullptr, 1.0f, 0);
}

// ---------------------------------------------------------------------------
// Flash attention, split-bf16 mma.sync. q-tile 128, kv-tile 64, 8 warps.
// R6: __launch_bounds__(256,2) -> 2 CTAs/SM (221KB smem of 228KB), 16 warps.
// ---------------------------------------------------------------------------
__global__ void __launch_bounds__(256, 2) flash_kernel(const float* __restrict__ prev)
{
    extern __shared__ char sm[];
    const uint32_t sb = smem_u32(sm);

    const int tid  = threadIdx.x;
    const int lane = tid & 31;
    const int w    = tid >> 5;
    const int bh   = blockIdx.y;
    const int b    = bh >> 4;
    const int hq   = bh & 15;
    const int q0   = blockIdx.x * QT;
    const int rq   = lane >> 2;
    const int cq   = (lane & 3) * 2;
    const int mrow = w * 16;

    const __nv_bfloat16* Qhg = g_qh + ((size_t)bh * S + q0) * 64;
    const __nv_bfloat16* Qlg = g_ql + ((size_t)bh * S + q0) * 64;
    const __nv_bfloat16* Khg = g_kh + (size_t)bh * S * 64;
    const __nv_bfloat16* Klg = g_kl + (size_t)bh * S * 64;
    const __nv_bfloat16* Vhg = g_vh + (size_t)bh * S * 64;
    const __nv_bfloat16* Vlg = g_vl + (size_t)bh * S * 64;

    // Q tiles (hi/lo) -> smem
#pragma unroll
    for (int it = 0; it < 8; ++it) {
        int i = tid + it * 256;
        int arr = i >> 10, r = (i >> 3) & 127, c = i & 7;
        const __nv_bfloat16* src = (arr ? Qlg : Qhg) + (size_t)r * 64 + c * 8;
        uint32_t dst = sb + (arr ? OFF_QL : OFF_QH) + (uint32_t)(r * (RP * 2) + c * 16);
        CPA16(dst, src);
    }

    auto load_kv = [&](int t, int buf) {
#pragma unroll
        for (int it = 0; it < 8; ++it) {
            int i = tid + it * 256;
            int arr = i >> 9, r = (i >> 3) & 63, c = i & 7;
            const __nv_bfloat16* base = (arr == 0) ? Khg : (arr == 1) ? Klg
                                      : (arr == 2) ? Vhg : Vlg;
            const __nv_bfloat16* src = base + (size_t)(t * KT + r) * 64 + c * 8;
            uint32_t dst = sb + OFF_KV + buf * KVBUF + arr * KVBYTES
                         + (uint32_t)(r * (RP * 2) + c * 16);
            CPA16(dst, src);
        }
        if (tid < 16) {
            uint32_t mv = *(const uint32_t*)(g_maskb + b * S + t * KT + tid * 4);
            *(uint32_t*)(sm + OFF_MK + buf * 64 + tid * 4) = mv;
        }
    };

    load_kv(0, 0);
    asm volatile("cp.async.commit_group;" ::: "memory");   // group: Q + kv0
    load_kv(1, 1);
    asm volatile("cp.async.commit_group;" ::: "memory");

    float m_i[2] = {-3.0e38f, -3.0e38f};
    float l_i[2] = {0.f, 0.f};
    float o[8][4];
#pragma unroll
    for (int j = 0; j < 8; ++j)
#pragma unroll
        for (int r = 0; r < 4; ++r) o[j][r] = 0.f;

    const float* prow0 = prev + ((size_t)bh * S + q0 + mrow + rq) * S;
    const float* prow1 = prow0 + (size_t)8 * S;

    for (int t = 0; t < NT; ++t) {
        const int buf = t & 1;
        if (t == NT - 1) asm volatile("cp.async.wait_group 0;" ::: "memory");
        else             asm volatile("cp.async.wait_group 1;" ::: "memory");
        __syncthreads();

        const uint32_t KH = sb + OFF_KV + buf * KVBUF;
        const uint32_t KL = KH + KVBYTES;
        const uint32_t VH = KL + KVBYTES;
        const uint32_t VL = VH + KVBYTES;
        const uint32_t QH = sb + OFF_QH, QL = sb + OFF_QL;

        // --- QK^T (split: QhKh + QhKl + QlKh) ---
        float s[8][4];
#pragma unroll
        for (int j = 0; j < 8; ++j)
#pragma unroll
            for (int r = 0; r < 4; ++r) s[j][r] = 0.f;

#pragma unroll
        for (int kc = 0; kc < 4; ++kc) {
            uint32_t aoff = (uint32_t)((mrow + (lane & 15)) * (RP * 2)
                                       + kc * 32 + (lane >> 4) * 16);
            uint32_t ah[4], al[4];
            ldsm4(ah, QH + aoff);
            ldsm4(al, QL + aoff);
#pragma unroll
            for (int jp = 0; jp < 4; ++jp) {
                uint32_t boff = (uint32_t)(((jp * 2 + (lane >> 4)) * 8 + (lane & 7)) * (RP * 2)
                                           + kc * 32 + ((lane >> 3) & 1) * 16);
                uint32_t bh4[4], bl4[4];
                ldsm4(bh4, KH + boff);
                ldsm4(bl4, KL + boff);
                MMA16816(s[2 * jp],     ah[0], ah[1], ah[2], ah[3], bh4[0], bh4[1]);
                MMA16816(s[2 * jp],     al[0], al[1], al[2], al[3], bh4[0], bh4[1]);
                MMA16816(s[2 * jp],     ah[0], ah[1], ah[2], ah[3], bl4[0], bl4[1]);
                MMA16816(s[2 * jp + 1], ah[0], ah[1], ah[2], ah[3], bh4[2], bh4[3]);
                MMA16816(s[2 * jp + 1], al[0], al[1], al[2], al[3], bh4[2], bh4[3]);
                MMA16816(s[2 * jp + 1], ah[0], ah[1], ah[2], ah[3], bl4[2], bl4[3]);
            }
        }

        // --- + prev, mask ---
#pragma unroll
        for (int j = 0; j < 8; ++j) {
            const unsigned char* mkp = (const unsigned char*)(sm + OFF_MK + buf * 64 + j * 8 + cq);
            unsigned char mk0 = mkp[0], mk1 = mkp[1];
            float2 p0 = *(const float2*)(prow0 + (size_t)t * KT + j * 8 + cq);
            float2 p1 = *(const float2*)(prow1 + (size_t)t * KT + j * 8 + cq);
            s[j][0] = mk0 ? -1.0e30f : s[j][0] + p0.x;
            s[j][1] = mk1 ? -1.0e30f : s[j][1] + p0.y;
            s[j][2] = mk0 ? -1.0e30f : s[j][2] + p1.x;
            s[j][3] = mk1 ? -1.0e30f : s[j][3] + p1.y;
        }

        // --- online softmax (rows rq, rq+8) ---
#pragma unroll
        for (int r = 0; r < 2; ++r) {
            float mx = -3.0e38f;
#pragma unroll
            for (int j = 0; j < 8; ++j)
                mx = fmaxf(mx, fmaxf(s[j][2 * r], s[j][2 * r + 1]));
            mx = fmaxf(mx, __shfl_xor_sync(0xffffffffu, mx, 1));
            mx = fmaxf(mx, __shfl_xor_sync(0xffffffffu, mx, 2));
            float m_new = fmaxf(m_i[r], mx);
            float corr  = __expf(m_i[r] - m_new);
            float rs = 0.f;
#pragma unroll
            for (int j = 0; j < 8; ++j) {
                s[j][2 * r]     = __expf(s[j][2 * r]     - m_new);
                s[j][2 * r + 1] = __expf(s[j][2 * r + 1] - m_new);
                rs += s[j][2 * r] + s[j][2 * r + 1];
            }
            rs += __shfl_xor_sync(0xffffffffu, rs, 1);
            rs += __shfl_xor_sync(0xffffffffu, rs, 2);
            l_i[r] = l_i[r] * corr + rs;
            m_i[r] = m_new;
#pragma unroll
            for (int j = 0; j < 8; ++j) {
                o[j][2 * r]     *= corr;
                o[j][2 * r + 1] *= corr;
            }
        }

        // --- P@V (split: PhVh + PlVh + PhVl), P direct from registers ---
#pragma unroll
        for (int kc2 = 0; kc2 < 4; ++kc2) {
            const int j0 = 2 * kc2, j1 = j0 + 1;
            uint32_t pah[4], pal[4];
#pragma unroll
            for (int q = 0; q < 4; ++q) {
                const int jt = (q & 2) ? j1 : j0;
                const int rr = (q & 1) ? 2 : 0;
                float x = s[jt][rr], y = s[jt][rr + 1];
                __nv_bfloat16 hx = __float2bfloat16(x);
                __nv_bfloat16 hy = __float2bfloat16(y);
                __nv_bfloat162 hp; hp.x = hx; hp.y = hy;
                __nv_bfloat162 lp;
                lp.x = __float2bfloat16(x - __bfloat162float(hx));
                lp.y = __float2bfloat16(y - __bfloat162float(hy));
                pah[q] = b2u(hp);
                pal[q] = b2u(lp);
            }
#pragma unroll
            for (int jp = 0; jp < 4; ++jp) {
                uint32_t voff = (uint32_t)((kc2 * 16 + ((lane >> 3) & 1) * 8 + (lane & 7)) * (RP * 2)
                                           + (jp * 2 + (lane >> 4)) * 16);
                uint32_t vh4[4], vl4[4];
                ldsm4t(vh4, VH + voff);
                ldsm4t(vl4, VL + voff);
                MMA16816(o[2 * jp],     pah[0], pah[1], pah[2], pah[3], vh4[0], vh4[1]);
                MMA16816(o[2 * jp],     pal[0], pal[1], pal[2], pal[3], vh4[0], vh4[1]);
                MMA16816(o[2 * jp],     pah[0], pah[1], pah[2], pah[3], vl4[0], vl4[1]);
                MMA16816(o[2 * jp + 1], pah[0], pah[1], pah[2], pah[3], vh4[2], vh4[3]);
                MMA16816(o[2 * jp + 1], pal[0], pal[1], pal[2], pal[3], vh4[2], vh4[3]);
                MMA16816(o[2 * jp + 1], pah[0], pah[1], pah[2], pah[3], vl4[2], vl4[3]);
            }
        }

        __syncthreads();
        if (t + 2 < NT) {
            load_kv(t + 2, buf);
            asm volatile("cp.async.commit_group;" ::: "memory");
        }
    }

    // --- epilogue: normalize, emit bf16 hi/lo attn [b][s][H*64] ---
    const float inv0 = 1.0f / fmaxf(l_i[0], 1e-30f);
    const float inv1 = 1.0f / fmaxf(l_i[1], 1e-30f);
    const size_t row0 = (size_t)b * S + q0 + mrow + rq;
#pragma unroll
    for (int jn = 0; jn < 8; ++jn) {
        const int col = hq * 64 + jn * 8 + cq;
        float v0 = o[jn][0] * inv0, v1 = o[jn][1] * inv0;
        float v2 = o[jn][2] * inv1, v3 = o[jn][3] * inv1;

        __nv_bfloat16 h0 = __float2bfloat16(v0), h1 = __float2bfloat16(v1);
        __nv_bfloat162 hp0; hp0.x = h0; hp0.y = h1;
        __nv_bfloat162 lp0;
        lp0.x = __float2bfloat16(v0 - __bfloat162float(h0));
        lp0.y = __float2bfloat16(v1 - __bfloat162float(h1));
        *(uint32_t*)(g_ah + row0 * 1024 + col) = b2u(hp0);
        *(uint32_t*)(g_al + row0 * 1024 + col) = b2u(lp0);

        __nv_bfloat16 h2 = __float2bfloat16(v2), h3 = __float2bfloat16(v3);
        __nv_bfloat162 hp1; hp1.x = h2; hp1.y = h3;
        __nv_bfloat162 lp1;
        lp1.x = __float2bfloat16(v2 - __bfloat162float(h2));
        lp1.y = __float2bfloat16(v3 - __bfloat162float(h3));
        *(uint32_t*)(g_ah + (row0 + 8) * 1024 + col) = b2u(hp1);
        *(uint32_t*)(g_al + (row0 + 8) * 1024 + col) = b2u(lp1);
    }
}

// ---------------------------------------------------------------------------
// Inputs: 0:q 1:k 2:v 3:prev 4:mask 5:Wq 6:bq 7:Wk 8:bk 9:Wv 10:bv 11:Wo 12:bo
// ---------------------------------------------------------------------------
extern "C" void kernel_launch(void* const* d_in, const int* in_sizes, int n_in,
                              void* d_out, int out_size)
{
    (void)in_sizes; (void)n_in; (void)out_size;

    const float* q    = (const float*)d_in[0];
    const float* kk   = (const float*)d_in[1];
    const float* v    = (const float*)d_in[2];
    const float* prev = (const float*)d_in[3];
    const unsigned char* mask = (const unsigned char*)d_in[4];
    const float* Wq = (const float*)d_in[5];
    const float* bq = (const float*)d_in[6];
    const float* Wk = (const float*)d_in[7];
    const float* bk = (const float*)d_in[8];
    const float* Wv = (const float*)d_in[9];
    const float* bv = (const float*)d_in[10];
    const float* Wo = (const float*)d_in[11];
    const float* bo = (const float*)d_in[12];
    float* out = (float*)d_out;

    cudaFuncSetAttribute(gemm_qkv_kernel,
                         cudaFuncAttributeMaxDynamicSharedMemorySize, SMEM_GEMM);
    cudaFuncSetAttribute(gemm_out_kernel,
                         cudaFuncAttributeMaxDynamicSharedMemorySize, SMEM_GEMM);
    cudaFuncSetAttribute(flash_kernel,
                         cudaFuncAttributeMaxDynamicSharedMemorySize, SMEM_FLASH);

    mask_prepare_kernel<<<1, 256>>>(mask);

    const int nX = M * D, nW = D * D;
    split_x_kernel<<<dim3(nX / 8 / 256, 1, 3), 256>>>(q, kk, v);
    split_w_kernel<<<dim3(nW / 8 / 256, 1, 4), 256>>>(Wq, Wk, Wv, Wo);

    gemm_qkv_kernel<<<dim3(D / BN, M / BM, 3), 256, SMEM_GEMM>>>(bq, bk, bv);
    flash_kernel<<<dim3(S / QT, Bb * H), 256, SMEM_FLASH>>>(prev);
    gemm_out_kernel<<<dim3(D / BN, M / BM), 256, SMEM_GEMM>>>(bo, out);
}

// round 7
// speedup vs baseline: 3.1286x; 1.1044x over previous
#include <cuda_runtime.h>
#include <cuda_bf16.h>
#include <cstdint>
#include <cstring>

// ---------------------------------------------------------------------------
// MultiHeadAttention B=2,S=2048,D=1024,H=16,DK=DV=64
// split-bf16 mma.sync everywhere: projections + flash attention.
// R7: GEMM inner loop on ldmatrix.x4 (12 LDSM vs 48 LDS per kk-step) and
//     2 CTAs/SM via __launch_bounds__(256,2).
// ---------------------------------------------------------------------------

namespace {
constexpr int  Bb = 2, S = 2048, D = 1024, H = 16;
constexpr int  M  = Bb * S;                    // 4096
constexpr float SCALE = 0.125f;

// projection GEMM tiling
constexpr int BM = 128, BN = 128, KCH = 32;
constexpr int NC = D / KCH;                    // 32 chunks
constexpr int ROWPAD = 40;                     // bf16 elems per smem row (80 B)
constexpr int TILE_B = 128 * ROWPAD * 2;
constexpr int BUF_B  = 4 * TILE_B;
constexpr int SMEM_GEMM = 2 * BUF_B;           // 81920 B

// flash tiling
constexpr int QT = 128, KT = 64, RP = 72;      // q tile, kv tile, padded row elems
constexpr int NT = S / KT;                     // 32 kv tiles
constexpr int QBYTES  = QT * RP * 2;           // 18432
constexpr int KVBYTES = KT * RP * 2;           // 9216
constexpr int OFF_QH = 0, OFF_QL = QBYTES;
constexpr int OFF_KV = 2 * QBYTES;             // 36864
constexpr int KVBUF  = 4 * KVBYTES;            // Kh,Kl,Vh,Vl = 36864
constexpr int OFF_MK = OFF_KV + 2 * KVBUF;     // 110592
constexpr int SMEM_FLASH = OFF_MK + 128;       // 110720
}

// ---- device scratch (allocation-free) ----
__device__ __nv_bfloat16 g_xh[3][(size_t)M * D];   // q,k,v inputs split hi
__device__ __nv_bfloat16 g_xl[3][(size_t)M * D];
__device__ __nv_bfloat16 g_wh[4][(size_t)D * D];   // Wq,Wk,Wv,Wo hi
__device__ __nv_bfloat16 g_wl[4][(size_t)D * D];
__device__ __nv_bfloat16 g_ah[(size_t)M * D];      // attn out hi
__device__ __nv_bfloat16 g_al[(size_t)M * D];
__device__ __nv_bfloat16 g_qh[(size_t)Bb * H * S * 64];  // per-head [bh][s][64]
__device__ __nv_bfloat16 g_ql[(size_t)Bb * H * S * 64];
__device__ __nv_bfloat16 g_kh[(size_t)Bb * H * S * 64];
__device__ __nv_bfloat16 g_kl[(size_t)Bb * H * S * 64];
__device__ __nv_bfloat16 g_vh[(size_t)Bb * H * S * 64];
__device__ __nv_bfloat16 g_vl[(size_t)Bb * H * S * 64];
__device__ unsigned char g_maskb[M];

// ---------------------------------------------------------------------------
// helpers
// ---------------------------------------------------------------------------
__device__ __forceinline__ uint32_t smem_u32(const void* p) {
    uint32_t a;
    asm("{ .reg .u64 t; cvta.to.shared.u64 t, %1; cvt.u32.u64 %0, t; }"
        : "=r"(a) : "l"(p));
    return a;
}
__device__ __forceinline__ void ldsm4(uint32_t* r, uint32_t a) {
    asm volatile("ldmatrix.sync.aligned.m8n8.x4.shared.b16 {%0,%1,%2,%3}, [%4];"
                 : "=r"(r[0]), "=r"(r[1]), "=r"(r[2]), "=r"(r[3]) : "r"(a));
}
__device__ __forceinline__ void ldsm4t(uint32_t* r, uint32_t a) {
    asm volatile("ldmatrix.sync.aligned.m8n8.x4.trans.shared.b16 {%0,%1,%2,%3}, [%4];"
                 : "=r"(r[0]), "=r"(r[1]), "=r"(r[2]), "=r"(r[3]) : "r"(a));
}
__device__ __forceinline__ uint32_t b2u(__nv_bfloat162 h) {
    uint32_t u;
    memcpy(&u, &h, 4);
    return u;
}
#define MMA16816(Dv, A0, A1, A2, A3, B0, B1)                                   \
    asm volatile(                                                              \
        "mma.sync.aligned.m16n8k16.row.col.f32.bf16.bf16.f32 "                 \
        "{%0,%1,%2,%3}, {%4,%5,%6,%7}, {%8,%9}, {%0,%1,%2,%3};"                \
        : "+f"((Dv)[0]), "+f"((Dv)[1]), "+f"((Dv)[2]), "+f"((Dv)[3])           \
        : "r"(A0), "r"(A1), "r"(A2), "r"(A3), "r"(B0), "r"(B1))
#define CPA16(dst, src)                                                        \
    asm volatile("cp.async.cg.shared.global [%0], [%1], 16;"                   \
                 :: "r"(dst), "l"(src) : "memory")

// ---------------------------------------------------------------------------
// Mask normalization (sniff bool/int32/float32 storage)
// ---------------------------------------------------------------------------
__global__ void mask_prepare_kernel(const unsigned char* __restrict__ raw)
{
    __shared__ int flags;
    if (threadIdx.x == 0) flags = 0;
    __syncthreads();
    int f = 0;
    for (int i = threadIdx.x; i < M; i += blockDim.x) {
        unsigned char c = raw[i];
        if ((i & 3) != 0 && c != 0) f |= 1;
        if ((i & 3) == 3 && c == 0x3F) f |= 2;
    }
    if (f) atomicOr(&flags, f);
    __syncthreads();
    const int fl = flags;
    for (int i = threadIdx.x; i < M; i += blockDim.x) {
        unsigned char v;
        if (fl & 2)      v = (((const float*)raw)[i] != 0.0f);
        else if (fl & 1) v = (raw[i] != 0);
        else             v = (((const int*)raw)[i] != 0);
        g_maskb[i] = v;
    }
}

// ---------------------------------------------------------------------------
// Fused fp32 -> bf16 hi/lo splits.
// ---------------------------------------------------------------------------
__device__ __forceinline__ void split8(const float* __restrict__ src,
                                       __nv_bfloat16* __restrict__ hi,
                                       __nv_bfloat16* __restrict__ lo,
                                       int i)
{
#pragma unroll
    for (int half = 0; half < 2; ++half) {
        float4 v = *(const float4*)(src + i + half * 4);
        float xs[4] = {v.x, v.y, v.z, v.w};
        __nv_bfloat16 hs[4], ls[4];
#pragma unroll
        for (int j = 0; j < 4; ++j) {
            hs[j] = __float2bfloat16(xs[j]);
            ls[j] = __float2bfloat16(xs[j] - __bfloat162float(hs[j]));
        }
        __nv_bfloat162 h0; h0.x = hs[0]; h0.y = hs[1];
        __nv_bfloat162 h1; h1.x = hs[2]; h1.y = hs[3];
        __nv_bfloat162 l0; l0.x = ls[0]; l0.y = ls[1];
        __nv_bfloat162 l1; l1.x = ls[2]; l1.y = ls[3];
        ((__nv_bfloat162*)(hi + i + half * 4))[0] = h0;
        ((__nv_bfloat162*)(hi + i + half * 4))[1] = h1;
        ((__nv_bfloat162*)(lo + i + half * 4))[0] = l0;
        ((__nv_bfloat162*)(lo + i + half * 4))[1] = l1;
    }
}

__global__ void __launch_bounds__(256) split_x_kernel(
    const float* __restrict__ q, const float* __restrict__ k,
    const float* __restrict__ v)
{
    const int z = blockIdx.z;
    const float* src = (z == 0) ? q : (z == 1 ? k : v);
    int i = (blockIdx.x * blockDim.x + threadIdx.x) * 8;
    split8(src, g_xh[z], g_xl[z], i);
}

__global__ void __launch_bounds__(256) split_w_kernel(
    const float* __restrict__ Wq, const float* __restrict__ Wk,
    const float* __restrict__ Wv, const float* __restrict__ Wo)
{
    const int z = blockIdx.z;
    const float* src = (z == 0) ? Wq : (z == 1 ? Wk : (z == 2 ? Wv : Wo));
    int i = (blockIdx.x * blockDim.x + threadIdx.x) * 8;
    split8(src, g_wh[z], g_wl[z], i);
}

// ---------------------------------------------------------------------------
// split-bf16 tensor-core GEMM: acc = X@W^T (+bias). Two epilogue modes:
//   mode 0: fp32 dst[m][D]           (final out-projection)
//   mode 1: bf16 hi/lo per-head [bh][s][64], value=(acc+bias)*scale
// R7: ldmatrix.x4 fragment loads, 2 CTAs/SM.
// ---------------------------------------------------------------------------
__device__ __forceinline__ void load_tile32(uint32_t sdst,
                                            const __nv_bfloat16* __restrict__ g,
                                            int row0, int k0)
{
#pragma unroll
    for (int it = 0; it < 2; ++it) {
        int i = threadIdx.x + it * 256;
        int r = i >> 2, c = i & 3;
        uint32_t dst = sdst + (uint32_t)(r * (ROWPAD * 2) + c * 16);
        const void* src = g + (size_t)(row0 + r) * D + k0 + c * 8;
        CPA16(dst, src);
    }
}

__device__ __forceinline__ void gemm_core(
    const __nv_bfloat16* __restrict__ Ah,
    const __nv_bfloat16* __restrict__ Al,
    const __nv_bfloat16* __restrict__ Bh,
    const __nv_bfloat16* __restrict__ Bl,
    const float* __restrict__ bias,
    float* __restrict__ dst,
    __nv_bfloat16* __restrict__ dsth,
    __nv_bfloat16* __restrict__ dstl,
    float scale, int mode)
{
    extern __shared__ char smraw[];
    const uint32_t sb = smem_u32(smraw);

    const int tid  = threadIdx.x;
    const int lane = tid & 31;
    const int wid  = tid >> 5;
    const int mw   = wid & 1;
    const int nw   = wid >> 1;
    const int m0   = blockIdx.y * BM;
    const int n0   = blockIdx.x * BN;

    auto tile = [&](int buf, int t) -> uint32_t { return sb + buf * BUF_B + t * TILE_B; };

    // ldmatrix lane-address components
    const int q8   = lane >> 3;        // quadrant 0..3
    const int l8   = lane & 7;         // row within 8-row group
    // A: mats [rows0-7,k0][rows8-15,k0][rows0-7,k8][rows8-15,k8]
    const int a_row = (q8 & 1) * 8 + l8;
    const int a_ke  = (q8 >> 1) * 8;
    // B: mats [j,k0][j,k8][j+1,k0][j+1,k8]
    const int b_row = (q8 >> 1) * 8 + l8;
    const int b_ke  = (q8 & 1) * 8;

    float d[4][4][4];
#pragma unroll
    for (int i = 0; i < 4; ++i)
#pragma unroll
        for (int j = 0; j < 4; ++j)
#pragma unroll
            for (int r = 0; r < 4; ++r) d[i][j][r] = 0.f;

#pragma unroll
    for (int p = 0; p < 2; ++p) {
        load_tile32(tile(p, 0), Ah, m0, p * KCH);
        load_tile32(tile(p, 1), Al, m0, p * KCH);
        load_tile32(tile(p, 2), Bh, n0, p * KCH);
        load_tile32(tile(p, 3), Bl, n0, p * KCH);
        asm volatile("cp.async.commit_group;" ::: "memory");
    }

    const int rq = lane >> 2;
    const int cq = (lane & 3) * 2;

    for (int c = 0; c < NC; ++c) {
        const int buf = c & 1;
        if (c == NC - 1) asm volatile("cp.async.wait_group 0;" ::: "memory");
        else             asm volatile("cp.async.wait_group 1;" ::: "memory");
        __syncthreads();

        const uint32_t xh = tile(buf, 0), xl = tile(buf, 1);
        const uint32_t wh = tile(buf, 2), wl = tile(buf, 3);

#pragma unroll
        for (int kk2 = 0; kk2 < 2; ++kk2) {
            const int kk = kk2 * 16;

            // B fragments: 2 ldmatrix.x4 per array -> all 4 j tiles
            uint32_t bhf[8], blf[8];      // [j*2 + word]
#pragma unroll
            for (int jp = 0; jp < 2; ++jp) {
                int rn = nw * 32 + jp * 16 + b_row;
                uint32_t off = (uint32_t)((rn * ROWPAD + kk + b_ke) * 2);
                uint32_t r4[4];
                ldsm4(r4, wh + off);
                bhf[jp * 4 + 0] = r4[0]; bhf[jp * 4 + 1] = r4[1];
                bhf[jp * 4 + 2] = r4[2]; bhf[jp * 4 + 3] = r4[3];
                ldsm4(r4, wl + off);
                blf[jp * 4 + 0] = r4[0]; blf[jp * 4 + 1] = r4[1];
                blf[jp * 4 + 2] = r4[2]; blf[jp * 4 + 3] = r4[3];
            }

#pragma unroll
            for (int mi = 0; mi < 4; ++mi) {
                int rm = mw * 64 + mi * 16 + a_row;
                uint32_t off = (uint32_t)((rm * ROWPAD + kk + a_ke) * 2);
                uint32_t a[4], al4[4];
                ldsm4(a, xh + off);
                ldsm4(al4, xl + off);
#pragma unroll
                for (int j = 0; j < 4; ++j) {
                    MMA16816(d[mi][j], a[0], a[1], a[2], a[3], bhf[j * 2], bhf[j * 2 + 1]);
                    MMA16816(d[mi][j], a[0], a[1], a[2], a[3], blf[j * 2], blf[j * 2 + 1]);
                    MMA16816(d[mi][j], al4[0], al4[1], al4[2], al4[3], bhf[j * 2], bhf[j * 2 + 1]);
                }
            }
        }
        __syncthreads();
        if (c + 2 < NC) {
            load_tile32(tile(buf, 0), Ah, m0, (c + 2) * KCH);
            load_tile32(tile(buf, 1), Al, m0, (c + 2) * KCH);
            load_tile32(tile(buf, 2), Bh, n0, (c + 2) * KCH);
            load_tile32(tile(buf, 3), Bl, n0, (c + 2) * KCH);
            asm volatile("cp.async.commit_group;" ::: "memory");
        }
    }

#pragma unroll
    for (int mi = 0; mi < 4; ++mi) {
#pragma unroll
        for (int j = 0; j < 4; ++j) {
            int r0 = m0 + mw * 64 + mi * 16 + rq;
            int n  = n0 + nw * 32 + j * 8 + cq;
            float b0 = bias[n], b1 = bias[n + 1];
#pragma unroll
            for (int h2 = 0; h2 < 2; ++h2) {
                int r = r0 + h2 * 8;
                float v0 = d[mi][j][h2 * 2 + 0] + b0;
                float v1 = d[mi][j][h2 * 2 + 1] + b1;
                if (mode == 0) {
                    float2 o; o.x = v0; o.y = v1;
                    *(float2*)(dst + (size_t)r * D + n) = o;
                } else {
                    v0 *= scale; v1 *= scale;
                    int b = r >> 11, srow = r & 2047;
                    int hh = n >> 6, dd = n & 63;
                    size_t base = (((size_t)(b * H + hh) * S + srow) << 6) + dd;
                    __nv_bfloat16 h0 = __float2bfloat16(v0);
                    __nv_bfloat16 h1 = __float2bfloat16(v1);
                    __nv_bfloat162 hp; hp.x = h0; hp.y = h1;
                    __nv_bfloat162 lp;
                    lp.x = __float2bfloat16(v0 - __bfloat162float(h0));
                    lp.y = __float2bfloat16(v1 - __bfloat162float(h1));
                    *(uint32_t*)(dsth + base) = b2u(hp);
                    *(uint32_t*)(dstl + base) = b2u(lp);
                }
            }
        }
    }
}

__global__ void __launch_bounds__(256, 2) gemm_qkv_kernel(
    const float* __restrict__ bq, const float* __restrict__ bk,
    const float* __restrict__ bv)
{
    const int z = blockIdx.z;
    const float* bias = (z == 0) ? bq : (z == 1 ? bk : bv);
    __nv_bfloat16* dh = (z == 0) ? g_qh : (z == 1 ? g_kh : g_vh);
    __nv_bfloat16* dl = (z == 0) ? g_ql : (z == 1 ? g_kl : g_vl);
    float scale = (z == 0) ? SCALE : 1.0f;
    gemm_core(g_xh[z], g_xl[z], g_wh[z], g_wl[z], bias,
              nullptr, dh, dl, scale, 1);
}

__global__ void __launch_bounds__(256, 2) gemm_out_kernel(
    const float* __restrict__ bo, float* __restrict__ out)
{
    gemm_core(g_ah, g_al, g_wh[3], g_wl[3], bo, out, nullptr, nullptr, 1.0f, 0);
}

// ---------------------------------------------------------------------------
// Flash attention, split-bf16 mma.sync. q-tile 128, kv-tile 64, 8 warps.
// 2 CTAs/SM.
// ---------------------------------------------------------------------------
__global__ void __launch_bounds__(256, 2) flash_kernel(const float* __restrict__ prev)
{
    extern __shared__ char sm[];
    const uint32_t sb = smem_u32(sm);

    const int tid  = threadIdx.x;
    const int lane = tid & 31;
    const int w    = tid >> 5;
    const int bh   = blockIdx.y;
    const int b    = bh >> 4;
    const int hq   = bh & 15;
    const int q0   = blockIdx.x * QT;
    const int rq   = lane >> 2;
    const int cq   = (lane & 3) * 2;
    const int mrow = w * 16;

    const __nv_bfloat16* Qhg = g_qh + ((size_t)bh * S + q0) * 64;
    const __nv_bfloat16* Qlg = g_ql + ((size_t)bh * S + q0) * 64;
    const __nv_bfloat16* Khg = g_kh + (size_t)bh * S * 64;
    const __nv_bfloat16* Klg = g_kl + (size_t)bh * S * 64;
    const __nv_bfloat16* Vhg = g_vh + (size_t)bh * S * 64;
    const __nv_bfloat16* Vlg = g_vl + (size_t)bh * S * 64;

    // Q tiles (hi/lo) -> smem
#pragma unroll
    for (int it = 0; it < 8; ++it) {
        int i = tid + it * 256;
        int arr = i >> 10, r = (i >> 3) & 127, c = i & 7;
        const __nv_bfloat16* src = (arr ? Qlg : Qhg) + (size_t)r * 64 + c * 8;
        uint32_t dst = sb + (arr ? OFF_QL : OFF_QH) + (uint32_t)(r * (RP * 2) + c * 16);
        CPA16(dst, src);
    }

    auto load_kv = [&](int t, int buf) {
#pragma unroll
        for (int it = 0; it < 8; ++it) {
            int i = tid + it * 256;
            int arr = i >> 9, r = (i >> 3) & 63, c = i & 7;
            const __nv_bfloat16* base = (arr == 0) ? Khg : (arr == 1) ? Klg
                                      : (arr == 2) ? Vhg : Vlg;
            const __nv_bfloat16* src = base + (size_t)(t * KT + r) * 64 + c * 8;
            uint32_t dst = sb + OFF_KV + buf * KVBUF + arr * KVBYTES
                         + (uint32_t)(r * (RP * 2) + c * 16);
            CPA16(dst, src);
        }
        if (tid < 16) {
            uint32_t mv = *(const uint32_t*)(g_maskb + b * S + t * KT + tid * 4);
            *(uint32_t*)(sm + OFF_MK + buf * 64 + tid * 4) = mv;
        }
    };

    load_kv(0, 0);
    asm volatile("cp.async.commit_group;" ::: "memory");   // group: Q + kv0
    load_kv(1, 1);
    asm volatile("cp.async.commit_group;" ::: "memory");

    float m_i[2] = {-3.0e38f, -3.0e38f};
    float l_i[2] = {0.f, 0.f};
    float o[8][4];
#pragma unroll
    for (int j = 0; j < 8; ++j)
#pragma unroll
        for (int r = 0; r < 4; ++r) o[j][r] = 0.f;

    const float* prow0 = prev + ((size_t)bh * S + q0 + mrow + rq) * S;
    const float* prow1 = prow0 + (size_t)8 * S;

    for (int t = 0; t < NT; ++t) {
        const int buf = t & 1;
        if (t == NT - 1) asm volatile("cp.async.wait_group 0;" ::: "memory");
        else             asm volatile("cp.async.wait_group 1;" ::: "memory");
        __syncthreads();

        const uint32_t KH = sb + OFF_KV + buf * KVBUF;
        const uint32_t KL = KH + KVBYTES;
        const uint32_t VH = KL + KVBYTES;
        const uint32_t VL = VH + KVBYTES;
        const uint32_t QH = sb + OFF_QH, QL = sb + OFF_QL;

        // --- QK^T (split: QhKh + QhKl + QlKh) ---
        float s[8][4];
#pragma unroll
        for (int j = 0; j < 8; ++j)
#pragma unroll
            for (int r = 0; r < 4; ++r) s[j][r] = 0.f;

#pragma unroll
        for (int kc = 0; kc < 4; ++kc) {
            uint32_t aoff = (uint32_t)((mrow + (lane & 15)) * (RP * 2)
                                       + kc * 32 + (lane >> 4) * 16);
            uint32_t ah[4], al[4];
            ldsm4(ah, QH + aoff);
            ldsm4(al, QL + aoff);
#pragma unroll
            for (int jp = 0; jp < 4; ++jp) {
                uint32_t boff = (uint32_t)(((jp * 2 + (lane >> 4)) * 8 + (lane & 7)) * (RP * 2)
                                           + kc * 32 + ((lane >> 3) & 1) * 16);
                uint32_t bh4[4], bl4[4];
                ldsm4(bh4, KH + boff);
                ldsm4(bl4, KL + boff);
                MMA16816(s[2 * jp],     ah[0], ah[1], ah[2], ah[3], bh4[0], bh4[1]);
                MMA16816(s[2 * jp],     al[0], al[1], al[2], al[3], bh4[0], bh4[1]);
                MMA16816(s[2 * jp],     ah[0], ah[1], ah[2], ah[3], bl4[0], bl4[1]);
                MMA16816(s[2 * jp + 1], ah[0], ah[1], ah[2], ah[3], bh4[2], bh4[3]);
                MMA16816(s[2 * jp + 1], al[0], al[1], al[2], al[3], bh4[2], bh4[3]);
                MMA16816(s[2 * jp + 1], ah[0], ah[1], ah[2], ah[3], bl4[2], bl4[3]);
            }
        }

        // --- + prev, mask ---
#pragma unroll
        for (int j = 0; j < 8; ++j) {
            const unsigned char* mkp = (const unsigned char*)(sm + OFF_MK + buf * 64 + j * 8 + cq);
            unsigned char mk0 = mkp[0], mk1 = mkp[1];
            float2 p0 = *(const float2*)(prow0 + (size_t)t * KT + j * 8 + cq);
            float2 p1 = *(const float2*)(prow1 + (size_t)t * KT + j * 8 + cq);
            s[j][0] = mk0 ? -1.0e30f : s[j][0] + p0.x;
            s[j][1] = mk1 ? -1.0e30f : s[j][1] + p0.y;
            s[j][2] = mk0 ? -1.0e30f : s[j][2] + p1.x;
            s[j][3] = mk1 ? -1.0e30f : s[j][3] + p1.y;
        }

        // --- online softmax (rows rq, rq+8) ---
#pragma unroll
        for (int r = 0; r < 2; ++r) {
            float mx = -3.0e38f;
#pragma unroll
            for (int j = 0; j < 8; ++j)
                mx = fmaxf(mx, fmaxf(s[j][2 * r], s[j][2 * r + 1]));
            mx = fmaxf(mx, __shfl_xor_sync(0xffffffffu, mx, 1));
            mx = fmaxf(mx, __shfl_xor_sync(0xffffffffu, mx, 2));
            float m_new = fmaxf(m_i[r], mx);
            float corr  = __expf(m_i[r] - m_new);
            float rs = 0.f;
#pragma unroll
            for (int j = 0; j < 8; ++j) {
                s[j][2 * r]     = __expf(s[j][2 * r]     - m_new);
                s[j][2 * r + 1] = __expf(s[j][2 * r + 1] - m_new);
                rs += s[j][2 * r] + s[j][2 * r + 1];
            }
            rs += __shfl_xor_sync(0xffffffffu, rs, 1);
            rs += __shfl_xor_sync(0xffffffffu, rs, 2);
            l_i[r] = l_i[r] * corr + rs;
            m_i[r] = m_new;
#pragma unroll
            for (int j = 0; j < 8; ++j) {
                o[j][2 * r]     *= corr;
                o[j][2 * r + 1] *= corr;
            }
        }

        // --- P@V (split: PhVh + PlVh + PhVl), P direct from registers ---
#pragma unroll
        for (int kc2 = 0; kc2 < 4; ++kc2) {
            const int j0 = 2 * kc2, j1 = j0 + 1;
            uint32_t pah[4], pal[4];
#pragma unroll
            for (int q = 0; q < 4; ++q) {
                const int jt = (q & 2) ? j1 : j0;
                const int rr = (q & 1) ? 2 : 0;
                float x = s[jt][rr], y = s[jt][rr + 1];
                __nv_bfloat16 hx = __float2bfloat16(x);
                __nv_bfloat16 hy = __float2bfloat16(y);
                __nv_bfloat162 hp; hp.x = hx; hp.y = hy;
                __nv_bfloat162 lp;
                lp.x = __float2bfloat16(x - __bfloat162float(hx));
                lp.y = __float2bfloat16(y - __bfloat162float(hy));
                pah[q] = b2u(hp);
                pal[q] = b2u(lp);
            }
#pragma unroll
            for (int jp = 0; jp < 4; ++jp) {
                uint32_t voff = (uint32_t)((kc2 * 16 + ((lane >> 3) & 1) * 8 + (lane & 7)) * (RP * 2)
                                           + (jp * 2 + (lane >> 4)) * 16);
                uint32_t vh4[4], vl4[4];
                ldsm4t(vh4, VH + voff);
                ldsm4t(vl4, VL + voff);
                MMA16816(o[2 * jp],     pah[0], pah[1], pah[2], pah[3], vh4[0], vh4[1]);
                MMA16816(o[2 * jp],     pal[0], pal[1], pal[2], pal[3], vh4[0], vh4[1]);
                MMA16816(o[2 * jp],     pah[0], pah[1], pah[2], pah[3], vl4[0], vl4[1]);
                MMA16816(o[2 * jp + 1], pah[0], pah[1], pah[2], pah[3], vh4[2], vh4[3]);
                MMA16816(o[2 * jp + 1], pal[0], pal[1], pal[2], pal[3], vh4[2], vh4[3]);
                MMA16816(o[2 * jp + 1], pah[0], pah[1], pah[2], pah[3], vl4[2], vl4[3]);
            }
        }

        __syncthreads();
        if (t + 2 < NT) {
            load_kv(t + 2, buf);
            asm volatile("cp.async.commit_group;" ::: "memory");
        }
    }

    // --- epilogue: normalize, emit bf16 hi/lo attn [b][s][H*64] ---
    const float inv0 = 1.0f / fmaxf(l_i[0], 1e-30f);
    const float inv1 = 1.0f / fmaxf(l_i[1], 1e-30f);
    const size_t row0 = (size_t)b * S + q0 + mrow + rq;
#pragma unroll
    for (int jn = 0; jn < 8; ++jn) {
        const int col = hq * 64 + jn * 8 + cq;
        float v0 = o[jn][0] * inv0, v1 = o[jn][1] * inv0;
        float v2 = o[jn][2] * inv1, v3 = o[jn][3] * inv1;

        __nv_bfloat16 h0 = __float2bfloat16(v0), h1 = __float2bfloat16(v1);
        __nv_bfloat162 hp0; hp0.x = h0; hp0.y = h1;
        __nv_bfloat162 lp0;
        lp0.x = __float2bfloat16(v0 - __bfloat162float(h0));
        lp0.y = __float2bfloat16(v1 - __bfloat162float(h1));
        *(uint32_t*)(g_ah + row0 * 1024 + col) = b2u(hp0);
        *(uint32_t*)(g_al + row0 * 1024 + col) = b2u(lp0);

        __nv_bfloat16 h2 = __float2bfloat16(v2), h3 = __float2bfloat16(v3);
        __nv_bfloat162 hp1; hp1.x = h2; hp1.y = h3;
        __nv_bfloat162 lp1;
        lp1.x = __float2bfloat16(v2 - __bfloat162float(h2));
        lp1.y = __float2bfloat16(v3 - __bfloat162float(h3));
        *(uint32_t*)(g_ah + (row0 + 8) * 1024 + col) = b2u(hp1);
        *(uint32_t*)(g_al + (row0 + 8) * 1024 + col) = b2u(lp1);
    }
}

// ---------------------------------------------------------------------------
// Inputs: 0:q 1:k 2:v 3:prev 4:mask 5:Wq 6:bq 7:Wk 8:bk 9:Wv 10:bv 11:Wo 12:bo
// ---------------------------------------------------------------------------
extern "C" void kernel_launch(void* const* d_in, const int* in_sizes, int n_in,
                              void* d_out, int out_size)
{
    (void)in_sizes; (void)n_in; (void)out_size;

    const float* q    = (const float*)d_in[0];
    const float* kk   = (const float*)d_in[1];
    const float* v    = (const float*)d_in[2];
    const float* prev = (const float*)d_in[3];
    const unsigned char* mask = (const unsigned char*)d_in[4];
    const float* Wq = (const float*)d_in[5];
    const float* bq = (const float*)d_in[6];
    const float* Wk = (const float*)d_in[7];
    const float* bk = (const float*)d_in[8];
    const float* Wv = (const float*)d_in[9];
    const float* bv = (const float*)d_in[10];
    const float* Wo = (const float*)d_in[11];
    const float* bo = (const float*)d_in[12];
    float* out = (float*)d_out;

    cudaFuncSetAttribute(gemm_qkv_kernel,
                         cudaFuncAttributeMaxDynamicSharedMemorySize, SMEM_GEMM);
    cudaFuncSetAttribute(gemm_out_kernel,
                         cudaFuncAttributeMaxDynamicSharedMemorySize, SMEM_GEMM);
    cudaFuncSetAttribute(flash_kernel,
                         cudaFuncAttributeMaxDynamicSharedMemorySize, SMEM_FLASH);

    mask_prepare_kernel<<<1, 256>>>(mask);

    const int nX = M * D, nW = D * D;
    split_x_kernel<<<dim3(nX / 8 / 256, 1, 3), 256>>>(q, kk, v);
    split_w_kernel<<<dim3(nW / 8 / 256, 1, 4), 256>>>(Wq, Wk, Wv, Wo);

    gemm_qkv_kernel<<<dim3(D / BN, M / BM, 3), 256, SMEM_GEMM>>>(bq, bk, bv);
    flash_kernel<<<dim3(S / QT, Bb * H), 256, SMEM_FLASH>>>(prev);
    gemm_out_kernel<<<dim3(D / BN, M / BM), 256, SMEM_GEMM>>>(bo, out);
}